// round 8
// baseline (speedup 1.0000x reference)
#include <cuda_runtime.h>
#include <cuda_bf16.h>
#include <stdint.h>
#include <math.h>

#define BB 32
#define S2 32
#define HH 1024
#define DHEAD 64
#define NLAY 4
#define THIST 8
#define TACT 8
#define HINN 512
#define MR (BB*S2)
#define WSOSPLIT 16
#define NW 20
#define KC 64
#define STAGE_BYTES 65536
#define TC_SMEM (1024 + 2*STAGE_BYTES)

__device__ float d_pe[S2*HH];
__device__ float d_tokens[MR*HH];
__device__ float d_h[MR*HH];
__device__ float d_qb[MR*HH];
__device__ float d_kb[MR*HH];
__device__ float d_vb[MR*HH];
__device__ float d_ctx[MR*HH];
__device__ float d_p0[MR*HH];
__device__ float d_p1[MR*HH];
__device__ float d_prev[NLAY][MR*HH];
__device__ float d_aemb[BB*TACT*HH];
__device__ float d_snew[BB*HINN];
__device__ float d_wsop[WSOSPLIT*BB*HINN];
__device__ __nv_bfloat16 d_wt_hi[(size_t)NW*HH*HH];
__device__ __nv_bfloat16 d_wt_lo[(size_t)NW*HH*HH];

// ---------------- helpers ---------------------------------------------------
#define SWZ128(o) ((o) ^ (((o) >> 3) & 0x70))

__device__ __forceinline__ uint32_t pack_bf(__nv_bfloat16 a, __nv_bfloat16 b){
  __nv_bfloat162 t; t.x = a; t.y = b;
  return *(uint32_t*)&t;
}

// legacy tensor-core mma (valid on all sm_80+ targets)
__device__ __forceinline__ void mma16816(float* c, const uint32_t* a, const uint32_t* b){
  asm volatile("mma.sync.aligned.m16n8k16.row.col.f32.bf16.bf16.f32 "
    "{%0,%1,%2,%3}, {%4,%5,%6,%7}, {%8,%9}, {%0,%1,%2,%3};"
    : "+f"(c[0]),"+f"(c[1]),"+f"(c[2]),"+f"(c[3])
    : "r"(a[0]),"r"(a[1]),"r"(a[2]),"r"(a[3]), "r"(b[0]),"r"(b[1]));
}

// ---------------- weight transpose + hi/lo split ----------------------------
__global__ void wcvt_kernel(const float* __restrict__ Wq, const float* __restrict__ Wk,
                            const float* __restrict__ Wv, const float* __restrict__ Wo,
                            const float* __restrict__ Wfc){
  __shared__ float tile[32][33];
  int z = blockIdx.z;
  const float* src;
  if (z < 4)       src = Wq  + (size_t)z*HH*HH;
  else if (z < 8)  src = Wk  + (size_t)(z-4)*HH*HH;
  else if (z < 12) src = Wv  + (size_t)(z-8)*HH*HH;
  else if (z < 16) src = Wo  + (size_t)(z-12)*HH*HH;
  else             src = Wfc + (size_t)(z-16)*HH*HH;
  __nv_bfloat16* dh = d_wt_hi + (size_t)z*HH*HH;
  __nv_bfloat16* dl = d_wt_lo + (size_t)z*HH*HH;
  int n0 = blockIdx.x*32, k0 = blockIdx.y*32;
  int tx = threadIdx.x, ty = threadIdx.y;
  #pragma unroll
  for (int i=0;i<4;i++)
    tile[ty+i*8][tx] = src[(size_t)(k0+ty+i*8)*HH + n0 + tx];
  __syncthreads();
  #pragma unroll
  for (int i=0;i<4;i++){
    float v = tile[tx][ty+i*8];
    __nv_bfloat16 h = __float2bfloat16(v);
    __nv_bfloat16 l = __float2bfloat16(v - __bfloat162float(h));
    size_t o = (size_t)(n0+ty+i*8)*HH + k0 + tx;
    dh[o] = h; dl[o] = l;
  }
}

// ---------------- tensor-core GEMM (mma.sync, 4 warps, 128x128 tile) --------
struct TCZ { const float* A; const __nv_bfloat16* Bh; const __nv_bfloat16* Bl;
             float* C; int kBeg, kEnd; };
struct TCArgs { TCZ z[3]; int ldc; };

// Stage layout: [0,16K) A-hi  [16K,32K) A-lo  [32K,48K) B-hi  [48K,64K) B-lo
__device__ __forceinline__ void stage_fill(char* sp, const TCZ& gz,
                                           int mBase, int nBase, int k0, int tid){
  #pragma unroll
  for (int i=0;i<8;i++){
    int f = tid + i*128, row = f>>3, u = f&7;
    const float* ap = gz.A + (size_t)(mBase+row)*HH + k0 + u*8;
    float4 a0 = *(const float4*)ap;
    float4 a1 = *(const float4*)(ap+4);
    float v[8] = {a0.x,a0.y,a0.z,a0.w,a1.x,a1.y,a1.z,a1.w};
    __nv_bfloat16 h[8], l[8];
    #pragma unroll
    for (int j=0;j<8;j++){
      h[j] = __float2bfloat16(v[j]);
      l[j] = __float2bfloat16(v[j] - __bfloat162float(h[j]));
    }
    uint32_t off = SWZ128((uint32_t)(row*128 + u*16));
    uint4 qh = { pack_bf(h[0],h[1]), pack_bf(h[2],h[3]), pack_bf(h[4],h[5]), pack_bf(h[6],h[7]) };
    uint4 ql = { pack_bf(l[0],l[1]), pack_bf(l[2],l[3]), pack_bf(l[4],l[5]), pack_bf(l[6],l[7]) };
    *(uint4*)(sp + off)         = qh;
    *(uint4*)(sp + 16384 + off) = ql;
  }
  #pragma unroll
  for (int i=0;i<8;i++){
    int f = tid + i*128, row = f>>3, u = f&7;
    size_t go = (size_t)(nBase+row)*HH + k0 + u*8;
    uint4 bh = *(const uint4*)(gz.Bh + go);
    uint4 bl = *(const uint4*)(gz.Bl + go);
    uint32_t off = SWZ128((uint32_t)(row*128 + u*16));
    *(uint4*)(sp + 32768 + off) = bh;
    *(uint4*)(sp + 49152 + off) = bl;
  }
}

__global__ void __launch_bounds__(128,1) gemm_tc(TCArgs ga){
  extern __shared__ char smem[];
  TCZ gz = ga.z[blockIdx.z];
  int mBase = blockIdx.y*128, nBase = blockIdx.x*128;
  int tid = threadIdx.x, wid = tid>>5, lid = tid&31;
  const int nc = (gz.kEnd - gz.kBeg)/KC;

  int wy = wid>>1, wx = wid&1;
  int r4 = lid>>2, q4 = lid&3;
  float acc[4][8][4];
  #pragma unroll
  for (int mt=0;mt<4;mt++)
    #pragma unroll
    for (int nt=0;nt<8;nt++)
      #pragma unroll
      for (int c=0;c<4;c++) acc[mt][nt][c]=0.f;

  stage_fill(smem+1024, gz, mBase, nBase, gz.kBeg, tid);
  __syncthreads();
  for (int t=0; t<nc; t++){
    char* sp = smem + 1024 + (t&1)*STAGE_BYTES;
    if (t+1 < nc)
      stage_fill(smem + 1024 + ((t+1)&1)*STAGE_BYTES, gz, mBase, nBase,
                 gz.kBeg + (t+1)*KC, tid);
    char* Ah = sp;           char* Al = sp + 16384;
    char* Bh = sp + 32768;   char* Bl = sp + 49152;
    #pragma unroll
    for (int ks=0; ks<4; ks++){
      uint32_t af[4][4];
      // A-hi fragments
      #pragma unroll
      for (int mt=0;mt<4;mt++){
        int row = wy*64 + mt*16 + r4;
        uint32_t cb = ks*32 + q4*4;
        af[mt][0] = *(const uint32_t*)(Ah + SWZ128((uint32_t)(row*128 + cb)));
        af[mt][1] = *(const uint32_t*)(Ah + SWZ128((uint32_t)((row+8)*128 + cb)));
        af[mt][2] = *(const uint32_t*)(Ah + SWZ128((uint32_t)(row*128 + cb + 16)));
        af[mt][3] = *(const uint32_t*)(Ah + SWZ128((uint32_t)((row+8)*128 + cb + 16)));
      }
      // Ah*Bh
      #pragma unroll
      for (int nt=0;nt<8;nt++){
        int n0 = wx*64 + nt*8 + r4;
        uint32_t cb = ks*32 + q4*4;
        uint32_t bf[2];
        bf[0] = *(const uint32_t*)(Bh + SWZ128((uint32_t)(n0*128 + cb)));
        bf[1] = *(const uint32_t*)(Bh + SWZ128((uint32_t)(n0*128 + cb + 16)));
        #pragma unroll
        for (int mt=0;mt<4;mt++) mma16816(acc[mt][nt], af[mt], bf);
      }
      // Ah*Bl
      #pragma unroll
      for (int nt=0;nt<8;nt++){
        int n0 = wx*64 + nt*8 + r4;
        uint32_t cb = ks*32 + q4*4;
        uint32_t bf[2];
        bf[0] = *(const uint32_t*)(Bl + SWZ128((uint32_t)(n0*128 + cb)));
        bf[1] = *(const uint32_t*)(Bl + SWZ128((uint32_t)(n0*128 + cb + 16)));
        #pragma unroll
        for (int mt=0;mt<4;mt++) mma16816(acc[mt][nt], af[mt], bf);
      }
      // Al*Bh
      #pragma unroll
      for (int mt=0;mt<4;mt++){
        int row = wy*64 + mt*16 + r4;
        uint32_t cb = ks*32 + q4*4;
        af[mt][0] = *(const uint32_t*)(Al + SWZ128((uint32_t)(row*128 + cb)));
        af[mt][1] = *(const uint32_t*)(Al + SWZ128((uint32_t)((row+8)*128 + cb)));
        af[mt][2] = *(const uint32_t*)(Al + SWZ128((uint32_t)(row*128 + cb + 16)));
        af[mt][3] = *(const uint32_t*)(Al + SWZ128((uint32_t)((row+8)*128 + cb + 16)));
      }
      #pragma unroll
      for (int nt=0;nt<8;nt++){
        int n0 = wx*64 + nt*8 + r4;
        uint32_t cb = ks*32 + q4*4;
        uint32_t bf[2];
        bf[0] = *(const uint32_t*)(Bh + SWZ128((uint32_t)(n0*128 + cb)));
        bf[1] = *(const uint32_t*)(Bh + SWZ128((uint32_t)(n0*128 + cb + 16)));
        #pragma unroll
        for (int mt=0;mt<4;mt++) mma16816(acc[mt][nt], af[mt], bf);
      }
    }
    __syncthreads();
  }
  #pragma unroll
  for (int mt=0;mt<4;mt++){
    #pragma unroll
    for (int nt=0;nt<8;nt++){
      int grow = mBase + wy*64 + mt*16 + r4;
      int gcol = nBase + wx*64 + nt*8 + q4*2;
      float* c0 = gz.C + (size_t)grow*ga.ldc + gcol;
      float* c1 = gz.C + (size_t)(grow+8)*ga.ldc + gcol;
      c0[0] = acc[mt][nt][0]; c0[1] = acc[mt][nt][1];
      c1[0] = acc[mt][nt][2]; c1[1] = acc[mt][nt][3];
    }
  }
}

// ---------------- small kernels (unchanged from passing R3) -----------------
__global__ void pe_kernel(){
  int pos = blockIdx.x;
  for (int d = threadIdx.x; d < HH; d += blockDim.x){
    double e = (double)(2*(d>>1)) / (double)HH;
    double ang = (double)pos / pow(10000.0, e);
    d_pe[pos*HH+d] = (float)((d&1) ? cos(ang) : sin(ang));
  }
}

__global__ void init_tokens(){
  int s = blockIdx.x, b = blockIdx.y;
  const float* src = nullptr;
  if (s < 2*THIST)       src = ((s&1) ? d_kb : d_qb) + (size_t)(b*THIST + (s>>1))*HH;
  else if (s == 2*THIST) src = d_vb + (size_t)b*HH;
  float* dst = d_tokens + (size_t)(b*S2+s)*HH;
  for (int d = threadIdx.x; d < HH; d += blockDim.x) dst[d] = src ? src[d] : 0.f;
}

__global__ void build_h(int step){
  int s = blockIdx.x, b = blockIdx.y;
  int pos_a = 2*THIST + 1 + 2*step;
  int L = pos_a + 1;
  float* tok = d_tokens + (size_t)(b*S2+s)*HH;
  float* hp  = d_h + (size_t)(b*S2+s)*HH;
  const float* ae = d_aemb + (size_t)(b*TACT + step)*HH;
  for (int d = threadIdx.x; d < HH; d += blockDim.x){
    float t;
    if (s == pos_a){ t = ae[d]; tok[d] = t; } else t = tok[d];
    hp[d] = t + ((s < L) ? d_pe[s*HH+d] : 0.f);
  }
}

struct GemmZ { const float* A; const float* W; float* C; int kBeg, kEnd, M, lda; };
struct GemmArgs { GemmZ z[4]; int ldc; int act; };

__global__ void __launch_bounds__(256,2) gemm_kernel(GemmArgs ga){
  GemmZ gz = ga.z[blockIdx.z];
  int mBase = blockIdx.y*128;
  if (mBase >= gz.M) return;
  int nBase = blockIdx.x*128;
  int tid = threadIdx.x, tx = tid&15, ty = tid>>4;
  __shared__ float As[2][16][128];
  __shared__ float Bs[2][16][128];
  int arow[2], ak4[2], brow[2], bc4[2]; bool aok[2];
  #pragma unroll
  for (int i=0;i<2;i++){
    int f = tid + i*256;
    arow[i]=f>>2; ak4[i]=f&3; aok[i]=(mBase+arow[i])<gz.M;
    brow[i]=f>>5; bc4[i]=f&31;
  }
  int nt = (gz.kEnd - gz.kBeg)>>4;
  float4 av[2], bv[2];
  {
    int k0 = gz.kBeg;
    #pragma unroll
    for (int i=0;i<2;i++){
      av[i] = aok[i] ? *(const float4*)(gz.A + (size_t)(mBase+arow[i])*gz.lda + k0 + ak4[i]*4)
                     : make_float4(0.f,0.f,0.f,0.f);
      bv[i] = *(const float4*)(gz.W + (size_t)(k0+brow[i])*HH + nBase + bc4[i]*4);
    }
    #pragma unroll
    for (int i=0;i<2;i++){
      As[0][ak4[i]*4+0][arow[i]]=av[i].x; As[0][ak4[i]*4+1][arow[i]]=av[i].y;
      As[0][ak4[i]*4+2][arow[i]]=av[i].z; As[0][ak4[i]*4+3][arow[i]]=av[i].w;
      *(float4*)&Bs[0][brow[i]][bc4[i]*4] = bv[i];
    }
  }
  __syncthreads();
  float acc[8][8];
  #pragma unroll
  for (int r=0;r<8;r++)
    #pragma unroll
    for (int c=0;c<8;c++) acc[r][c]=0.f;
  int buf=0;
  for (int t=0;t<nt;t++){
    if (t+1<nt){
      int k0 = gz.kBeg + (t+1)*16;
      #pragma unroll
      for (int i=0;i<2;i++){
        av[i] = aok[i] ? *(const float4*)(gz.A + (size_t)(mBase+arow[i])*gz.lda + k0 + ak4[i]*4)
                       : make_float4(0.f,0.f,0.f,0.f);
        bv[i] = *(const float4*)(gz.W + (size_t)(k0+brow[i])*HH + nBase + bc4[i]*4);
      }
    }
    #pragma unroll
    for (int kk=0;kk<16;kk++){
      float4 a0=*(const float4*)&As[buf][kk][ty*8];
      float4 a1=*(const float4*)&As[buf][kk][ty*8+4];
      float4 b0=*(const float4*)&Bs[buf][kk][tx*8];
      float4 b1=*(const float4*)&Bs[buf][kk][tx*8+4];
      float a[8]={a0.x,a0.y,a0.z,a0.w,a1.x,a1.y,a1.z,a1.w};
      float bb[8]={b0.x,b0.y,b0.z,b0.w,b1.x,b1.y,b1.z,b1.w};
      #pragma unroll
      for (int r=0;r<8;r++)
        #pragma unroll
        for (int c=0;c<8;c++) acc[r][c]=fmaf(a[r],bb[c],acc[r][c]);
    }
    if (t+1<nt){
      buf^=1;
      #pragma unroll
      for (int i=0;i<2;i++){
        As[buf][ak4[i]*4+0][arow[i]]=av[i].x; As[buf][ak4[i]*4+1][arow[i]]=av[i].y;
        As[buf][ak4[i]*4+2][arow[i]]=av[i].z; As[buf][ak4[i]*4+3][arow[i]]=av[i].w;
        *(float4*)&Bs[buf][brow[i]][bc4[i]*4]=bv[i];
      }
      __syncthreads();
    }
  }
  #pragma unroll
  for (int r=0;r<8;r++){
    int grow = mBase + ty*8 + r;
    if (grow < gz.M){
      float* cp = gz.C + (size_t)grow*ga.ldc + nBase + tx*8;
      #pragma unroll
      for (int c=0;c<8;c++){
        float v = acc[r][c];
        if (ga.act) v = v>0.f ? v : 0.f;
        cp[c] = v;
      }
    }
  }
}

__global__ void attn_kernel(int L){
  __shared__ float Qs[S2][DHEAD];
  __shared__ float Ks[S2][DHEAD+1];
  __shared__ float Vs[S2][DHEAD];
  __shared__ float Ps[S2][S2+1];
  int bh = blockIdx.x, b = bh>>4, hd = bh&15, tid = threadIdx.x;
  const float* qb = d_qb + (size_t)(b*S2)*HH + hd*DHEAD;
  const float* kb = d_kb + (size_t)(b*S2)*HH + hd*DHEAD;
  const float* vb = d_vb + (size_t)(b*S2)*HH + hd*DHEAD;
  for (int i = tid; i < S2*DHEAD; i += blockDim.x){
    int s=i>>6, d=i&63;
    Qs[s][d]=qb[(size_t)s*HH+d]; Ks[s][d]=kb[(size_t)s*HH+d]; Vs[s][d]=vb[(size_t)s*HH+d];
  }
  __syncthreads();
  for (int i = tid; i < S2*S2; i += blockDim.x){
    int q=i>>5, k=i&31;
    float sc=0.f;
    #pragma unroll
    for (int d=0;d<DHEAD;d++) sc += Qs[q][d]*Ks[k][d];
    sc *= 0.125f;
    if (!(q<L && k<L)) sc = -1e20f;
    Ps[q][k]=sc;
  }
  __syncthreads();
  if (tid < S2){
    int q = tid;
    if (q >= L){ for (int k=0;k<S2;k++) Ps[q][k]=0.f; }
    else {
      float mx=-3.4e38f;
      for (int k=0;k<S2;k++) mx = fmaxf(mx, Ps[q][k]);
      float sum=0.f;
      for (int k=0;k<S2;k++){ float e=expf(Ps[q][k]-mx); Ps[q][k]=e; sum+=e; }
      float inv=1.f/sum;
      for (int k=0;k<S2;k++) Ps[q][k] = (k<L) ? Ps[q][k]*inv : 0.f;
    }
  }
  __syncthreads();
  for (int i = tid; i < S2*DHEAD; i += blockDim.x){
    int q=i>>6, d=i&63;
    float o=0.f;
    #pragma unroll
    for (int k=0;k<S2;k++) o += Ps[q][k]*Vs[k][d];
    d_ctx[(size_t)(b*S2+q)*HH + hd*DHEAD + d] = o;
  }
}

__device__ __forceinline__ float block_sum(float v){
  __shared__ float red[32];
  int lane=threadIdx.x&31, wid=threadIdx.x>>5;
  #pragma unroll
  for (int o=16;o>0;o>>=1) v += __shfl_down_sync(0xffffffffu, v, o);
  if (lane==0) red[wid]=v;
  __syncthreads();
  float r = (threadIdx.x < (blockDim.x>>5)) ? red[threadIdx.x] : 0.f;
  if (wid==0){
    #pragma unroll
    for (int o=16;o>0;o>>=1) r += __shfl_down_sync(0xffffffffu, r, o);
    if (lane==0) red[0]=r;
  }
  __syncthreads();
  float out = red[0];
  __syncthreads();
  return out;
}

__global__ void ln_kernel(const float* __restrict__ x, const float* __restrict__ p0,
                          const float* __restrict__ p1, const float* __restrict__ g,
                          const float* __restrict__ bia, float* out, float* out2){
  int row = blockIdx.x, tid = threadIdx.x;
  float v[4]; float s=0.f;
  #pragma unroll
  for (int i=0;i<4;i++){
    size_t off = (size_t)row*HH + tid + i*256;
    float t = x[off]+p0[off]+p1[off];
    v[i]=t; s+=t;
  }
  float mean = block_sum(s)*(1.f/HH);
  float s2=0.f;
  #pragma unroll
  for (int i=0;i<4;i++){ float dd=v[i]-mean; s2+=dd*dd; }
  float inv = 1.f/sqrtf(block_sum(s2)*(1.f/HH) + 1e-5f);
  #pragma unroll
  for (int i=0;i<4;i++){
    int d = tid + i*256;
    size_t off = (size_t)row*HH + d;
    float y = (v[i]-mean)*inv*g[d] + bia[d];
    out[off]=y;
    if (out2) out2[off]=y;
  }
}

__global__ void wr_kernel(const float* __restrict__ Wr, float* out, int step){
  int b = blockIdx.x;
  float s=0.f;
  const float* hf = d_h + (size_t)b*S2*HH;
  for (int x = threadIdx.x; x < S2*HH; x += blockDim.x) s += hf[x]*Wr[x];
  s = block_sum(s);
  if (threadIdx.x==0) out[b*TACT+step] = 1.f/(1.f+expf(-s));
}

__global__ void wso_part(const float* __restrict__ Wso){
  int nb = blockIdx.x, sp = blockIdx.y, tid = threadIdx.x;
  int tx = tid&63, tg = tid>>6;
  __shared__ float Asm[32][33];
  __shared__ float Wsm[32][64];
  float acc[8];
  #pragma unroll
  for (int r=0;r<8;r++) acc[r]=0.f;
  const int kLen = (S2*HH)/WSOSPLIT, k0 = sp*kLen;
  for (int kc=0; kc<kLen; kc+=32){
    for (int i=tid; i<32*32; i+=256){
      int bq=i>>5, kk=i&31;
      Asm[bq][kk] = d_h[(size_t)bq*S2*HH + k0+kc+kk];
    }
    for (int i=tid; i<32*64; i+=256){
      int kk=i>>6, cc=i&63;
      Wsm[kk][cc] = Wso[(size_t)(k0+kc+kk)*HINN + nb*64 + cc];
    }
    __syncthreads();
    #pragma unroll
    for (int kk=0;kk<32;kk++){
      float w = Wsm[kk][tx];
      #pragma unroll
      for (int r=0;r<8;r++) acc[r] = fmaf(Asm[tg*8+r][kk], w, acc[r]);
    }
    __syncthreads();
  }
  #pragma unroll
  for (int r=0;r<8;r++)
    d_wsop[(size_t)sp*BB*HINN + (size_t)(tg*8+r)*HINN + nb*64 + tx] = acc[r];
}

__global__ void wso_reduce(float* out, int step){
  int b = blockIdx.x, n = threadIdx.x;
  float s=0.f;
  #pragma unroll
  for (int sp=0;sp<WSOSPLIT;sp++) s += d_wsop[(size_t)sp*BB*HINN + (size_t)b*HINN + n];
  s = fmaxf(s, 0.f);
  d_snew[b*HINN+n] = s;
  out[BB*TACT + (size_t)(b*TACT+step)*HINN + n] = s;
}

static void* sym(const void* s){ void* p = nullptr; cudaGetSymbolAddress(&p, s); return p; }

extern "C" void kernel_launch(void* const* d_in, const int* in_sizes, int n_in,
                              void* d_out, int out_size){
  (void)in_sizes; (void)n_in; (void)out_size;
  const float* hist_s=(const float*)d_in[0];
  const float* hist_a=(const float*)d_in[1];
  const float* s_in  =(const float*)d_in[2];
  const float* a_list=(const float*)d_in[3];
  const float* Ws =(const float*)d_in[4];
  const float* Wa =(const float*)d_in[5];
  const float* Wq =(const float*)d_in[6];
  const float* Wk =(const float*)d_in[7];
  const float* Wv =(const float*)d_in[8];
  const float* Wo =(const float*)d_in[9];
  const float* Wfc=(const float*)d_in[10];
  const float* ln1g=(const float*)d_in[11];
  const float* ln1b=(const float*)d_in[12];
  const float* ln2g=(const float*)d_in[13];
  const float* ln2b=(const float*)d_in[14];
  const float* Wr =(const float*)d_in[15];
  const float* Wso=(const float*)d_in[16];
  float* out = (float*)d_out;

  float* ph   =(float*)sym(d_h);
  float* pq   =(float*)sym(d_qb);
  float* pk   =(float*)sym(d_kb);
  float* pv   =(float*)sym(d_vb);
  float* pctx =(float*)sym(d_ctx);
  float* pp0  =(float*)sym(d_p0);
  float* pp1  =(float*)sym(d_p1);
  float* pprev=(float*)sym(d_prev);
  float* pae  =(float*)sym(d_aemb);
  float* psn  =(float*)sym(d_snew);
  float* ptok =(float*)sym(d_tokens);
  __nv_bfloat16* pwh = (__nv_bfloat16*)sym(d_wt_hi);
  __nv_bfloat16* pwl = (__nv_bfloat16*)sym(d_wt_lo);

  cudaFuncSetAttribute(gemm_tc, cudaFuncAttributeMaxDynamicSharedMemorySize, TC_SMEM);

  pe_kernel<<<S2,256>>>();
  wcvt_kernel<<<dim3(32,32,NW),dim3(32,8)>>>(Wq, Wk, Wv, Wo, Wfc);

  {
    GemmArgs ga{};
    ga.ldc=HH; ga.act=1;
    ga.z[0]=GemmZ{hist_s, Ws, pq, 0, HINN, BB*THIST, HINN};
    ga.z[1]=GemmZ{hist_a, Wa, pk, 0, 64,   BB*THIST, 64};
    ga.z[2]=GemmZ{s_in,   Ws, pv, 0, HINN, BB,       HINN};
    ga.z[3]=GemmZ{a_list, Wa, pae,0, 64,   BB*TACT,  64};
    gemm_kernel<<<dim3(8,2,4),256>>>(ga);
  }
  init_tokens<<<dim3(S2,BB),256>>>();

  const size_t WSZ = (size_t)HH*HH;
  for (int i=0;i<TACT;i++){
    int L = 2*THIST + 2 + 2*i;
    build_h<<<dim3(S2,BB),256>>>(i);
    for (int j=0;j<NLAY;j++){
      const float* qk = (i==0) ? ph : (pprev + (size_t)j*MR*HH);
      {
        TCArgs ga{};
        ga.ldc=HH;
        ga.z[0]=TCZ{qk, pwh + (size_t)(0*4+j)*WSZ,  pwl + (size_t)(0*4+j)*WSZ,  pq, 0, HH};
        ga.z[1]=TCZ{qk, pwh + (size_t)(1*4+j)*WSZ,  pwl + (size_t)(1*4+j)*WSZ,  pk, 0, HH};
        ga.z[2]=TCZ{ph, pwh + (size_t)(2*4+j)*WSZ,  pwl + (size_t)(2*4+j)*WSZ,  pv, 0, HH};
        gemm_tc<<<dim3(8,8,3),128,TC_SMEM>>>(ga);
      }
      attn_kernel<<<BB*16,256>>>(L);
      {
        TCArgs ga{};
        ga.ldc=HH;
        ga.z[0]=TCZ{pctx, pwh + (size_t)(3*4+j)*WSZ, pwl + (size_t)(3*4+j)*WSZ, pp0, 0,    HH/2};
        ga.z[1]=TCZ{pctx, pwh + (size_t)(3*4+j)*WSZ, pwl + (size_t)(3*4+j)*WSZ, pp1, HH/2, HH};
        gemm_tc<<<dim3(8,8,2),128,TC_SMEM>>>(ga);
      }
      ln_kernel<<<MR,256>>>(ph, pp0, pp1, ln1g+(size_t)j*HH, ln1b+(size_t)j*HH, ph, nullptr);
      {
        TCArgs ga{};
        ga.ldc=HH;
        ga.z[0]=TCZ{ph, pwh + (size_t)(4*4+j)*WSZ, pwl + (size_t)(4*4+j)*WSZ, pp0, 0,    HH/2};
        ga.z[1]=TCZ{ph, pwh + (size_t)(4*4+j)*WSZ, pwl + (size_t)(4*4+j)*WSZ, pp1, HH/2, HH};
        gemm_tc<<<dim3(8,8,2),128,TC_SMEM>>>(ga);
      }
      ln_kernel<<<MR,256>>>(ph, pp0, pp1, ln2g+(size_t)j*HH, ln2b+(size_t)j*HH, ph,
                            pprev + (size_t)j*MR*HH);
    }
    wr_kernel<<<BB,1024>>>(Wr, out, i);
    wso_part<<<dim3(8,WSOSPLIT),256>>>(Wso);
    wso_reduce<<<BB,HINN>>>(out, i);
    if (i+1 < TACT){
      int pos_s = 2*THIST + 2 + 2*i;
      GemmArgs ga{};
      ga.ldc=S2*HH; ga.act=1;
      ga.z[0]=GemmZ{psn, Ws, ptok + (size_t)pos_s*HH, 0, HINN, BB, HINN};
      gemm_kernel<<<dim3(8,1,1),256>>>(ga);
    }
  }
}

// round 12
// speedup vs baseline: 1.7724x; 1.7724x over previous
#include <cuda_runtime.h>
#include <cuda_bf16.h>
#include <stdint.h>
#include <math.h>

#define BB 32
#define S2 32
#define HH 1024
#define DHEAD 64
#define NLAY 4
#define THIST 8
#define TACT 8
#define HINN 512
#define MR (BB*S2)
#define WSOSPLIT 16
#define NW 20
#define KC 64
#define TC_SMEM 65536

__device__ float d_pe[S2*HH];
__device__ float d_tokens[MR*HH];
__device__ float d_h[MR*HH];
__device__ float d_qb[MR*HH];
__device__ float d_kb[MR*HH];
__device__ float d_vb[MR*HH];
__device__ float d_ctx[MR*HH];
__device__ float d_p0[MR*HH];
__device__ float d_p1[MR*HH];
__device__ float d_prev[NLAY][MR*HH];
__device__ float d_aemb[BB*TACT*HH];
__device__ float d_snew[BB*HINN];
__device__ float d_wsop[WSOSPLIT*BB*HINN];
__device__ __nv_bfloat16 d_wt_hi[(size_t)NW*HH*HH];
__device__ __nv_bfloat16 d_wt_lo[(size_t)NW*HH*HH];

// ---------------- helpers ---------------------------------------------------
#define SWZ128(o) ((o) ^ (((o) >> 3) & 0x70))

__device__ __forceinline__ uint32_t pack_bf(__nv_bfloat16 a, __nv_bfloat16 b){
  __nv_bfloat162 t; t.x = a; t.y = b;
  return *(uint32_t*)&t;
}

__device__ __forceinline__ void mma16816(float* c, const uint32_t* a, const uint32_t* b){
  asm volatile("mma.sync.aligned.m16n8k16.row.col.f32.bf16.bf16.f32 "
    "{%0,%1,%2,%3}, {%4,%5,%6,%7}, {%8,%9}, {%0,%1,%2,%3};"
    : "+f"(c[0]),"+f"(c[1]),"+f"(c[2]),"+f"(c[3])
    : "r"(a[0]),"r"(a[1]),"r"(a[2]),"r"(a[3]), "r"(b[0]),"r"(b[1]));
}

// ---------------- weight transpose + hi/lo split ----------------------------
__global__ void wcvt_kernel(const float* __restrict__ Wq, const float* __restrict__ Wk,
                            const float* __restrict__ Wv, const float* __restrict__ Wo,
                            const float* __restrict__ Wfc){
  __shared__ float tile[32][33];
  int z = blockIdx.z;
  const float* src;
  if (z < 4)       src = Wq  + (size_t)z*HH*HH;
  else if (z < 8)  src = Wk  + (size_t)(z-4)*HH*HH;
  else if (z < 12) src = Wv  + (size_t)(z-8)*HH*HH;
  else if (z < 16) src = Wo  + (size_t)(z-12)*HH*HH;
  else             src = Wfc + (size_t)(z-16)*HH*HH;
  __nv_bfloat16* dh = d_wt_hi + (size_t)z*HH*HH;
  __nv_bfloat16* dl = d_wt_lo + (size_t)z*HH*HH;
  int n0 = blockIdx.x*32, k0 = blockIdx.y*32;
  int tx = threadIdx.x, ty = threadIdx.y;
  #pragma unroll
  for (int i=0;i<4;i++)
    tile[ty+i*8][tx] = src[(size_t)(k0+ty+i*8)*HH + n0 + tx];
  __syncthreads();
  #pragma unroll
  for (int i=0;i<4;i++){
    float v = tile[tx][ty+i*8];
    __nv_bfloat16 h = __float2bfloat16(v);
    __nv_bfloat16 l = __float2bfloat16(v - __bfloat162float(h));
    size_t o = (size_t)(n0+ty+i*8)*HH + k0 + tx;
    dh[o] = h; dl[o] = l;
  }
}

// ---------------- tensor-core GEMM (mma.sync, 8 warps, 128x128 tile) --------
struct TCZ { const float* A; const __nv_bfloat16* Bh; const __nv_bfloat16* Bl;
             float* C; int kBeg, kEnd; };
struct TCArgs { TCZ z[3]; int ldc; };

// Stage layout: [0,16K) A-hi  [16K,32K) A-lo  [32K,48K) B-hi  [48K,64K) B-lo
__device__ __forceinline__ void stage_fill(char* sp, const TCZ& gz,
                                           int mBase, int nBase, int k0, int tid){
  #pragma unroll
  for (int i=0;i<4;i++){
    int f = tid + i*256, row = f>>3, u = f&7;
    const float* ap = gz.A + (size_t)(mBase+row)*HH + k0 + u*8;
    float4 a0 = *(const float4*)ap;
    float4 a1 = *(const float4*)(ap+4);
    float v[8] = {a0.x,a0.y,a0.z,a0.w,a1.x,a1.y,a1.z,a1.w};
    __nv_bfloat16 h[8], l[8];
    #pragma unroll
    for (int j=0;j<8;j++){
      h[j] = __float2bfloat16(v[j]);
      l[j] = __float2bfloat16(v[j] - __bfloat162float(h[j]));
    }
    uint32_t off = SWZ128((uint32_t)(row*128 + u*16));
    uint4 qh = { pack_bf(h[0],h[1]), pack_bf(h[2],h[3]), pack_bf(h[4],h[5]), pack_bf(h[6],h[7]) };
    uint4 ql = { pack_bf(l[0],l[1]), pack_bf(l[2],l[3]), pack_bf(l[4],l[5]), pack_bf(l[6],l[7]) };
    *(uint4*)(sp + off)         = qh;
    *(uint4*)(sp + 16384 + off) = ql;
  }
  #pragma unroll
  for (int i=0;i<4;i++){
    int f = tid + i*256, row = f>>3, u = f&7;
    size_t go = (size_t)(nBase+row)*HH + k0 + u*8;
    uint4 bh = *(const uint4*)(gz.Bh + go);
    uint4 bl = *(const uint4*)(gz.Bl + go);
    uint32_t off = SWZ128((uint32_t)(row*128 + u*16));
    *(uint4*)(sp + 32768 + off) = bh;
    *(uint4*)(sp + 49152 + off) = bl;
  }
}

__global__ void __launch_bounds__(256,2) gemm_tc(TCArgs ga){
  extern __shared__ char smem[];
  TCZ gz = ga.z[blockIdx.z];
  int mBase = blockIdx.y*128, nBase = blockIdx.x*128;
  int tid = threadIdx.x, wid = tid>>5, lid = tid&31;
  const int nc = (gz.kEnd - gz.kBeg)/KC;

  // 8 warps: 2 (m) x 4 (n); warp tile 64x32 => mt=4 (16-row), nt=4 (8-col)
  int wy = wid>>2, wx = wid&3;
  int r4 = lid>>2, q4 = lid&3;
  float acc[4][4][4];
  #pragma unroll
  for (int mt=0;mt<4;mt++)
    #pragma unroll
    for (int nt=0;nt<4;nt++)
      #pragma unroll
      for (int c=0;c<4;c++) acc[mt][nt][c]=0.f;

  for (int t=0; t<nc; t++){
    __syncthreads();
    stage_fill(smem, gz, mBase, nBase, gz.kBeg + t*KC, tid);
    __syncthreads();
    char* Ah = smem;          char* Al = smem + 16384;
    char* Bh = smem + 32768;  char* Bl = smem + 49152;
    #pragma unroll
    for (int ks=0; ks<4; ks++){
      uint32_t cb = (uint32_t)(ks*32 + q4*4);
      uint32_t af[4][4];
      // ---- pass 1: A-hi; products Ah*Bh and Ah*Bl ----
      #pragma unroll
      for (int mt=0;mt<4;mt++){
        int row = wy*64 + mt*16 + r4;
        af[mt][0] = *(const uint32_t*)(Ah + SWZ128((uint32_t)(row*128 + cb)));
        af[mt][1] = *(const uint32_t*)(Ah + SWZ128((uint32_t)((row+8)*128 + cb)));
        af[mt][2] = *(const uint32_t*)(Ah + SWZ128((uint32_t)(row*128 + cb + 16)));
        af[mt][3] = *(const uint32_t*)(Ah + SWZ128((uint32_t)((row+8)*128 + cb + 16)));
      }
      #pragma unroll
      for (int nt=0;nt<4;nt++){
        int n0 = wx*32 + nt*8 + r4;
        uint32_t bh[2], bl[2];
        bh[0] = *(const uint32_t*)(Bh + SWZ128((uint32_t)(n0*128 + cb)));
        bh[1] = *(const uint32_t*)(Bh + SWZ128((uint32_t)(n0*128 + cb + 16)));
        bl[0] = *(const uint32_t*)(Bl + SWZ128((uint32_t)(n0*128 + cb)));
        bl[1] = *(const uint32_t*)(Bl + SWZ128((uint32_t)(n0*128 + cb + 16)));
        #pragma unroll
        for (int mt=0;mt<4;mt++){
          mma16816(acc[mt][nt], af[mt], bh);
          mma16816(acc[mt][nt], af[mt], bl);
        }
      }
      // ---- pass 2: A-lo; product Al*Bh (reuse A frag registers) ----
      #pragma unroll
      for (int mt=0;mt<4;mt++){
        int row = wy*64 + mt*16 + r4;
        af[mt][0] = *(const uint32_t*)(Al + SWZ128((uint32_t)(row*128 + cb)));
        af[mt][1] = *(const uint32_t*)(Al + SWZ128((uint32_t)((row+8)*128 + cb)));
        af[mt][2] = *(const uint32_t*)(Al + SWZ128((uint32_t)(row*128 + cb + 16)));
        af[mt][3] = *(const uint32_t*)(Al + SWZ128((uint32_t)((row+8)*128 + cb + 16)));
      }
      #pragma unroll
      for (int nt=0;nt<4;nt++){
        int n0 = wx*32 + nt*8 + r4;
        uint32_t bh[2];
        bh[0] = *(const uint32_t*)(Bh + SWZ128((uint32_t)(n0*128 + cb)));
        bh[1] = *(const uint32_t*)(Bh + SWZ128((uint32_t)(n0*128 + cb + 16)));
        #pragma unroll
        for (int mt=0;mt<4;mt++)
          mma16816(acc[mt][nt], af[mt], bh);
      }
    }
  }
  #pragma unroll
  for (int mt=0;mt<4;mt++){
    #pragma unroll
    for (int nt=0;nt<4;nt++){
      int grow = mBase + wy*64 + mt*16 + r4;
      int gcol = nBase + wx*32 + nt*8 + q4*2;
      float* c0 = gz.C + (size_t)grow*ga.ldc + gcol;
      float* c1 = gz.C + (size_t)(grow+8)*ga.ldc + gcol;
      c0[0] = acc[mt][nt][0]; c0[1] = acc[mt][nt][1];
      c1[0] = acc[mt][nt][2]; c1[1] = acc[mt][nt][3];
    }
  }
}

// ---------------- small kernels (unchanged) ---------------------------------
__global__ void pe_kernel(){
  int pos = blockIdx.x;
  for (int d = threadIdx.x; d < HH; d += blockDim.x){
    double e = (double)(2*(d>>1)) / (double)HH;
    double ang = (double)pos / pow(10000.0, e);
    d_pe[pos*HH+d] = (float)((d&1) ? cos(ang) : sin(ang));
  }
}

__global__ void init_tokens(){
  int s = blockIdx.x, b = blockIdx.y;
  const float* src = nullptr;
  if (s < 2*THIST)       src = ((s&1) ? d_kb : d_qb) + (size_t)(b*THIST + (s>>1))*HH;
  else if (s == 2*THIST) src = d_vb + (size_t)b*HH;
  float* dst = d_tokens + (size_t)(b*S2+s)*HH;
  for (int d = threadIdx.x; d < HH; d += blockDim.x) dst[d] = src ? src[d] : 0.f;
}

__global__ void build_h(int step){
  int s = blockIdx.x, b = blockIdx.y;
  int pos_a = 2*THIST + 1 + 2*step;
  int L = pos_a + 1;
  float* tok = d_tokens + (size_t)(b*S2+s)*HH;
  float* hp  = d_h + (size_t)(b*S2+s)*HH;
  const float* ae = d_aemb + (size_t)(b*TACT + step)*HH;
  for (int d = threadIdx.x; d < HH; d += blockDim.x){
    float t;
    if (s == pos_a){ t = ae[d]; tok[d] = t; } else t = tok[d];
    hp[d] = t + ((s < L) ? d_pe[s*HH+d] : 0.f);
  }
}

struct GemmZ { const float* A; const float* W; float* C; int kBeg, kEnd, M, lda; };
struct GemmArgs { GemmZ z[4]; int ldc; int act; };

__global__ void __launch_bounds__(256,2) gemm_kernel(GemmArgs ga){
  GemmZ gz = ga.z[blockIdx.z];
  int mBase = blockIdx.y*128;
  if (mBase >= gz.M) return;
  int nBase = blockIdx.x*128;
  int tid = threadIdx.x, tx = tid&15, ty = tid>>4;
  __shared__ float As[2][16][128];
  __shared__ float Bs[2][16][128];
  int arow[2], ak4[2], brow[2], bc4[2]; bool aok[2];
  #pragma unroll
  for (int i=0;i<2;i++){
    int f = tid + i*256;
    arow[i]=f>>2; ak4[i]=f&3; aok[i]=(mBase+arow[i])<gz.M;
    brow[i]=f>>5; bc4[i]=f&31;
  }
  int nt = (gz.kEnd - gz.kBeg)>>4;
  float4 av[2], bv[2];
  {
    int k0 = gz.kBeg;
    #pragma unroll
    for (int i=0;i<2;i++){
      av[i] = aok[i] ? *(const float4*)(gz.A + (size_t)(mBase+arow[i])*gz.lda + k0 + ak4[i]*4)
                     : make_float4(0.f,0.f,0.f,0.f);
      bv[i] = *(const float4*)(gz.W + (size_t)(k0+brow[i])*HH + nBase + bc4[i]*4);
    }
    #pragma unroll
    for (int i=0;i<2;i++){
      As[0][ak4[i]*4+0][arow[i]]=av[i].x; As[0][ak4[i]*4+1][arow[i]]=av[i].y;
      As[0][ak4[i]*4+2][arow[i]]=av[i].z; As[0][ak4[i]*4+3][arow[i]]=av[i].w;
      *(float4*)&Bs[0][brow[i]][bc4[i]*4] = bv[i];
    }
  }
  __syncthreads();
  float acc[8][8];
  #pragma unroll
  for (int r=0;r<8;r++)
    #pragma unroll
    for (int c=0;c<8;c++) acc[r][c]=0.f;
  int buf=0;
  for (int t=0;t<nt;t++){
    if (t+1<nt){
      int k0 = gz.kBeg + (t+1)*16;
      #pragma unroll
      for (int i=0;i<2;i++){
        av[i] = aok[i] ? *(const float4*)(gz.A + (size_t)(mBase+arow[i])*gz.lda + k0 + ak4[i]*4)
                       : make_float4(0.f,0.f,0.f,0.f);
        bv[i] = *(const float4*)(gz.W + (size_t)(k0+brow[i])*HH + nBase + bc4[i]*4);
      }
    }
    #pragma unroll
    for (int kk=0;kk<16;kk++){
      float4 a0=*(const float4*)&As[buf][kk][ty*8];
      float4 a1=*(const float4*)&As[buf][kk][ty*8+4];
      float4 b0=*(const float4*)&Bs[buf][kk][tx*8];
      float4 b1=*(const float4*)&Bs[buf][kk][tx*8+4];
      float a[8]={a0.x,a0.y,a0.z,a0.w,a1.x,a1.y,a1.z,a1.w};
      float bb[8]={b0.x,b0.y,b0.z,b0.w,b1.x,b1.y,b1.z,b1.w};
      #pragma unroll
      for (int r=0;r<8;r++)
        #pragma unroll
        for (int c=0;c<8;c++) acc[r][c]=fmaf(a[r],bb[c],acc[r][c]);
    }
    if (t+1<nt){
      buf^=1;
      #pragma unroll
      for (int i=0;i<2;i++){
        As[buf][ak4[i]*4+0][arow[i]]=av[i].x; As[buf][ak4[i]*4+1][arow[i]]=av[i].y;
        As[buf][ak4[i]*4+2][arow[i]]=av[i].z; As[buf][ak4[i]*4+3][arow[i]]=av[i].w;
        *(float4*)&Bs[buf][brow[i]][bc4[i]*4]=bv[i];
      }
      __syncthreads();
    }
  }
  #pragma unroll
  for (int r=0;r<8;r++){
    int grow = mBase + ty*8 + r;
    if (grow < gz.M){
      float* cp = gz.C + (size_t)grow*ga.ldc + nBase + tx*8;
      #pragma unroll
      for (int c=0;c<8;c++){
        float v = acc[r][c];
        if (ga.act) v = v>0.f ? v : 0.f;
        cp[c] = v;
      }
    }
  }
}

__global__ void attn_kernel(int L){
  __shared__ float Qs[S2][DHEAD];
  __shared__ float Ks[S2][DHEAD+1];
  __shared__ float Vs[S2][DHEAD];
  __shared__ float Ps[S2][S2+1];
  int bh = blockIdx.x, b = bh>>4, hd = bh&15, tid = threadIdx.x;
  const float* qb = d_qb + (size_t)(b*S2)*HH + hd*DHEAD;
  const float* kb = d_kb + (size_t)(b*S2)*HH + hd*DHEAD;
  const float* vb = d_vb + (size_t)(b*S2)*HH + hd*DHEAD;
  for (int i = tid; i < S2*DHEAD; i += blockDim.x){
    int s=i>>6, d=i&63;
    Qs[s][d]=qb[(size_t)s*HH+d]; Ks[s][d]=kb[(size_t)s*HH+d]; Vs[s][d]=vb[(size_t)s*HH+d];
  }
  __syncthreads();
  for (int i = tid; i < S2*S2; i += blockDim.x){
    int q=i>>5, k=i&31;
    float sc=0.f;
    #pragma unroll
    for (int d=0;d<DHEAD;d++) sc += Qs[q][d]*Ks[k][d];
    sc *= 0.125f;
    if (!(q<L && k<L)) sc = -1e20f;
    Ps[q][k]=sc;
  }
  __syncthreads();
  if (tid < S2){
    int q = tid;
    if (q >= L){ for (int k=0;k<S2;k++) Ps[q][k]=0.f; }
    else {
      float mx=-3.4e38f;
      for (int k=0;k<S2;k++) mx = fmaxf(mx, Ps[q][k]);
      float sum=0.f;
      for (int k=0;k<S2;k++){ float e=expf(Ps[q][k]-mx); Ps[q][k]=e; sum+=e; }
      float inv=1.f/sum;
      for (int k=0;k<S2;k++) Ps[q][k] = (k<L) ? Ps[q][k]*inv : 0.f;
    }
  }
  __syncthreads();
  for (int i = tid; i < S2*DHEAD; i += blockDim.x){
    int q=i>>6, d=i&63;
    float o=0.f;
    #pragma unroll
    for (int k=0;k<S2;k++) o += Ps[q][k]*Vs[k][d];
    d_ctx[(size_t)(b*S2+q)*HH + hd*DHEAD + d] = o;
  }
}

__device__ __forceinline__ float block_sum(float v){
  __shared__ float red[32];
  int lane=threadIdx.x&31, wid=threadIdx.x>>5;
  #pragma unroll
  for (int o=16;o>0;o>>=1) v += __shfl_down_sync(0xffffffffu, v, o);
  if (lane==0) red[wid]=v;
  __syncthreads();
  float r = (threadIdx.x < (blockDim.x>>5)) ? red[threadIdx.x] : 0.f;
  if (wid==0){
    #pragma unroll
    for (int o=16;o>0;o>>=1) r += __shfl_down_sync(0xffffffffu, r, o);
    if (lane==0) red[0]=r;
  }
  __syncthreads();
  float out = red[0];
  __syncthreads();
  return out;
}

__global__ void ln_kernel(const float* __restrict__ x, const float* __restrict__ p0,
                          const float* __restrict__ p1, const float* __restrict__ g,
                          const float* __restrict__ bia, float* out, float* out2){
  int row = blockIdx.x, tid = threadIdx.x;
  float v[4]; float s=0.f;
  #pragma unroll
  for (int i=0;i<4;i++){
    size_t off = (size_t)row*HH + tid + i*256;
    float t = x[off]+p0[off]+p1[off];
    v[i]=t; s+=t;
  }
  float mean = block_sum(s)*(1.f/HH);
  float s2=0.f;
  #pragma unroll
  for (int i=0;i<4;i++){ float dd=v[i]-mean; s2+=dd*dd; }
  float inv = 1.f/sqrtf(block_sum(s2)*(1.f/HH) + 1e-5f);
  #pragma unroll
  for (int i=0;i<4;i++){
    int d = tid + i*256;
    size_t off = (size_t)row*HH + d;
    float y = (v[i]-mean)*inv*g[d] + bia[d];
    out[off]=y;
    if (out2) out2[off]=y;
  }
}

__global__ void wr_kernel(const float* __restrict__ Wr, float* out, int step){
  int b = blockIdx.x;
  float s=0.f;
  const float* hf = d_h + (size_t)b*S2*HH;
  for (int x = threadIdx.x; x < S2*HH; x += blockDim.x) s += hf[x]*Wr[x];
  s = block_sum(s);
  if (threadIdx.x==0) out[b*TACT+step] = 1.f/(1.f+expf(-s));
}

__global__ void wso_part(const float* __restrict__ Wso){
  int nb = blockIdx.x, sp = blockIdx.y, tid = threadIdx.x;
  int tx = tid&63, tg = tid>>6;
  __shared__ float Asm[32][33];
  __shared__ float Wsm[32][64];
  float acc[8];
  #pragma unroll
  for (int r=0;r<8;r++) acc[r]=0.f;
  const int kLen = (S2*HH)/WSOSPLIT, k0 = sp*kLen;
  for (int kc=0; kc<kLen; kc+=32){
    for (int i=tid; i<32*32; i+=256){
      int bq=i>>5, kk=i&31;
      Asm[bq][kk] = d_h[(size_t)bq*S2*HH + k0+kc+kk];
    }
    for (int i=tid; i<32*64; i+=256){
      int kk=i>>6, cc=i&63;
      Wsm[kk][cc] = Wso[(size_t)(k0+kc+kk)*HINN + nb*64 + cc];
    }
    __syncthreads();
    #pragma unroll
    for (int kk=0;kk<32;kk++){
      float w = Wsm[kk][tx];
      #pragma unroll
      for (int r=0;r<8;r++) acc[r] = fmaf(Asm[tg*8+r][kk], w, acc[r]);
    }
    __syncthreads();
  }
  #pragma unroll
  for (int r=0;r<8;r++)
    d_wsop[(size_t)sp*BB*HINN + (size_t)(tg*8+r)*HINN + nb*64 + tx] = acc[r];
}

__global__ void wso_reduce(float* out, int step){
  int b = blockIdx.x, n = threadIdx.x;
  float s=0.f;
  #pragma unroll
  for (int sp=0;sp<WSOSPLIT;sp++) s += d_wsop[(size_t)sp*BB*HINN + (size_t)b*HINN + n];
  s = fmaxf(s, 0.f);
  d_snew[b*HINN+n] = s;
  out[BB*TACT + (size_t)(b*TACT+step)*HINN + n] = s;
}

static void* sym(const void* s){ void* p = nullptr; cudaGetSymbolAddress(&p, s); return p; }

extern "C" void kernel_launch(void* const* d_in, const int* in_sizes, int n_in,
                              void* d_out, int out_size){
  (void)in_sizes; (void)n_in; (void)out_size;
  const float* hist_s=(const float*)d_in[0];
  const float* hist_a=(const float*)d_in[1];
  const float* s_in  =(const float*)d_in[2];
  const float* a_list=(const float*)d_in[3];
  const float* Ws =(const float*)d_in[4];
  const float* Wa =(const float*)d_in[5];
  const float* Wq =(const float*)d_in[6];
  const float* Wk =(const float*)d_in[7];
  const float* Wv =(const float*)d_in[8];
  const float* Wo =(const float*)d_in[9];
  const float* Wfc=(const float*)d_in[10];
  const float* ln1g=(const float*)d_in[11];
  const float* ln1b=(const float*)d_in[12];
  const float* ln2g=(const float*)d_in[13];
  const float* ln2b=(const float*)d_in[14];
  const float* Wr =(const float*)d_in[15];
  const float* Wso=(const float*)d_in[16];
  float* out = (float*)d_out;

  float* ph   =(float*)sym(d_h);
  float* pq   =(float*)sym(d_qb);
  float* pk   =(float*)sym(d_kb);
  float* pv   =(float*)sym(d_vb);
  float* pctx =(float*)sym(d_ctx);
  float* pp0  =(float*)sym(d_p0);
  float* pp1  =(float*)sym(d_p1);
  float* pprev=(float*)sym(d_prev);
  float* pae  =(float*)sym(d_aemb);
  float* psn  =(float*)sym(d_snew);
  float* ptok =(float*)sym(d_tokens);
  __nv_bfloat16* pwh = (__nv_bfloat16*)sym(d_wt_hi);
  __nv_bfloat16* pwl = (__nv_bfloat16*)sym(d_wt_lo);

  cudaFuncSetAttribute(gemm_tc, cudaFuncAttributeMaxDynamicSharedMemorySize, TC_SMEM);

  pe_kernel<<<S2,256>>>();
  wcvt_kernel<<<dim3(32,32,NW),dim3(32,8)>>>(Wq, Wk, Wv, Wo, Wfc);

  {
    GemmArgs ga{};
    ga.ldc=HH; ga.act=1;
    ga.z[0]=GemmZ{hist_s, Ws, pq, 0, HINN, BB*THIST, HINN};
    ga.z[1]=GemmZ{hist_a, Wa, pk, 0, 64,   BB*THIST, 64};
    ga.z[2]=GemmZ{s_in,   Ws, pv, 0, HINN, BB,       HINN};
    ga.z[3]=GemmZ{a_list, Wa, pae,0, 64,   BB*TACT,  64};
    gemm_kernel<<<dim3(8,2,4),256>>>(ga);
  }
  init_tokens<<<dim3(S2,BB),256>>>();

  const size_t WSZ = (size_t)HH*HH;
  for (int i=0;i<TACT;i++){
    int L = 2*THIST + 2 + 2*i;
    build_h<<<dim3(S2,BB),256>>>(i);
    for (int j=0;j<NLAY;j++){
      const float* qk = (i==0) ? ph : (pprev + (size_t)j*MR*HH);
      {
        TCArgs ga{};
        ga.ldc=HH;
        ga.z[0]=TCZ{qk, pwh + (size_t)(0*4+j)*WSZ,  pwl + (size_t)(0*4+j)*WSZ,  pq, 0, HH};
        ga.z[1]=TCZ{qk, pwh + (size_t)(1*4+j)*WSZ,  pwl + (size_t)(1*4+j)*WSZ,  pk, 0, HH};
        ga.z[2]=TCZ{ph, pwh + (size_t)(2*4+j)*WSZ,  pwl + (size_t)(2*4+j)*WSZ,  pv, 0, HH};
        gemm_tc<<<dim3(8,8,3),256,TC_SMEM>>>(ga);
      }
      attn_kernel<<<BB*16,256>>>(L);
      {
        TCArgs ga{};
        ga.ldc=HH;
        ga.z[0]=TCZ{pctx, pwh + (size_t)(3*4+j)*WSZ, pwl + (size_t)(3*4+j)*WSZ, pp0, 0,    HH/2};
        ga.z[1]=TCZ{pctx, pwh + (size_t)(3*4+j)*WSZ, pwl + (size_t)(3*4+j)*WSZ, pp1, HH/2, HH};
        gemm_tc<<<dim3(8,8,2),256,TC_SMEM>>>(ga);
      }
      ln_kernel<<<MR,256>>>(ph, pp0, pp1, ln1g+(size_t)j*HH, ln1b+(size_t)j*HH, ph, nullptr);
      {
        TCArgs ga{};
        ga.ldc=HH;
        ga.z[0]=TCZ{ph, pwh + (size_t)(4*4+j)*WSZ, pwl + (size_t)(4*4+j)*WSZ, pp0, 0,    HH/2};
        ga.z[1]=TCZ{ph, pwh + (size_t)(4*4+j)*WSZ, pwl + (size_t)(4*4+j)*WSZ, pp1, HH/2, HH};
        gemm_tc<<<dim3(8,8,2),256,TC_SMEM>>>(ga);
      }
      ln_kernel<<<MR,256>>>(ph, pp0, pp1, ln2g+(size_t)j*HH, ln2b+(size_t)j*HH, ph,
                            pprev + (size_t)j*MR*HH);
    }
    wr_kernel<<<BB,1024>>>(Wr, out, i);
    wso_part<<<dim3(8,WSOSPLIT),256>>>(Wso);
    wso_reduce<<<BB,HINN>>>(out, i);
    if (i+1 < TACT){
      int pos_s = 2*THIST + 2 + 2*i;
      GemmArgs ga{};
      ga.ldc=S2*HH; ga.act=1;
      ga.z[0]=GemmZ{psn, Ws, ptok + (size_t)pos_s*HH, 0, HINN, BB, HINN};
      gemm_kernel<<<dim3(8,1,1),256>>>(ga);
    }
  }
}

// round 13
// speedup vs baseline: 2.3434x; 1.3222x over previous
#include <cuda_runtime.h>
#include <cuda_bf16.h>
#include <stdint.h>
#include <math.h>

#define BB 32
#define S2 32
#define HH 1024
#define DHEAD 64
#define NLAY 4
#define THIST 8
#define TACT 8
#define HINN 512
#define MR (BB*S2)
#define WSOSPLIT 16
#define NW 20
#define KC 32
#define TC_SMEM 65536

__device__ float d_pe[S2*HH];
__device__ float d_tokens[MR*HH];
__device__ float d_h[MR*HH];
__device__ float d_qb[MR*HH];
__device__ float d_kb[MR*HH];
__device__ float d_vb[MR*HH];
__device__ float d_p0[MR*HH];
__device__ float d_p1[MR*HH];
__device__ float d_aemb[BB*TACT*HH];
__device__ float d_snew[BB*HINN];
__device__ float d_wsop[WSOSPLIT*BB*HINN];
__device__ __nv_bfloat16 d_h_hi[MR*HH];
__device__ __nv_bfloat16 d_h_lo[MR*HH];
__device__ __nv_bfloat16 d_ctx_hi[MR*HH];
__device__ __nv_bfloat16 d_ctx_lo[MR*HH];
__device__ __nv_bfloat16 d_prev_hi[NLAY][MR*HH];
__device__ __nv_bfloat16 d_prev_lo[NLAY][MR*HH];
__device__ __nv_bfloat16 d_wt_hi[(size_t)NW*HH*HH];
__device__ __nv_bfloat16 d_wt_lo[(size_t)NW*HH*HH];

// ---------------- helpers ---------------------------------------------------
#define SWZ128(o) ((o) ^ (((o) >> 3) & 0x70))

__device__ __forceinline__ uint32_t smem_u32(const void* p){
  uint32_t a;
  asm("{ .reg .u64 t; cvta.to.shared.u64 t, %1; cvt.u32.u64 %0, t; }" : "=r"(a) : "l"(p));
  return a;
}
__device__ __forceinline__ void cpa16(uint32_t d, const void* s){
  asm volatile("cp.async.cg.shared.global [%0], [%1], 16;" :: "r"(d), "l"(s));
}
#define CP_COMMIT() asm volatile("cp.async.commit_group;" ::: "memory")
#define CP_WAIT1()  asm volatile("cp.async.wait_group 1;" ::: "memory")
#define CP_WAIT0()  asm volatile("cp.async.wait_group 0;" ::: "memory")

__device__ __forceinline__ void split_bf(float v, __nv_bfloat16& h, __nv_bfloat16& l){
  h = __float2bfloat16(v);
  l = __float2bfloat16(v - __bfloat162float(h));
}

__device__ __forceinline__ void mma16816(float* c, const uint32_t* a, const uint32_t* b){
  asm volatile("mma.sync.aligned.m16n8k16.row.col.f32.bf16.bf16.f32 "
    "{%0,%1,%2,%3}, {%4,%5,%6,%7}, {%8,%9}, {%0,%1,%2,%3};"
    : "+f"(c[0]),"+f"(c[1]),"+f"(c[2]),"+f"(c[3])
    : "r"(a[0]),"r"(a[1]),"r"(a[2]),"r"(a[3]), "r"(b[0]),"r"(b[1]));
}

// ---------------- weight transpose + hi/lo split ----------------------------
__global__ void wcvt_kernel(const float* __restrict__ Wq, const float* __restrict__ Wk,
                            const float* __restrict__ Wv, const float* __restrict__ Wo,
                            const float* __restrict__ Wfc){
  __shared__ float tile[32][33];
  int z = blockIdx.z;
  const float* src;
  if (z < 4)       src = Wq  + (size_t)z*HH*HH;
  else if (z < 8)  src = Wk  + (size_t)(z-4)*HH*HH;
  else if (z < 12) src = Wv  + (size_t)(z-8)*HH*HH;
  else if (z < 16) src = Wo  + (size_t)(z-12)*HH*HH;
  else             src = Wfc + (size_t)(z-16)*HH*HH;
  __nv_bfloat16* dh = d_wt_hi + (size_t)z*HH*HH;
  __nv_bfloat16* dl = d_wt_lo + (size_t)z*HH*HH;
  int n0 = blockIdx.x*32, k0 = blockIdx.y*32;
  int tx = threadIdx.x, ty = threadIdx.y;
  #pragma unroll
  for (int i=0;i<4;i++)
    tile[ty+i*8][tx] = src[(size_t)(k0+ty+i*8)*HH + n0 + tx];
  __syncthreads();
  #pragma unroll
  for (int i=0;i<4;i++){
    float v = tile[tx][ty+i*8];
    __nv_bfloat16 h, l; split_bf(v, h, l);
    size_t o = (size_t)(n0+ty+i*8)*HH + k0 + tx;
    dh[o] = h; dl[o] = l;
  }
}

// ---------------- tensor-core GEMM (cp.async pipelined, 8 warps) ------------
struct TCZ { const __nv_bfloat16 *Ah, *Al, *Bh, *Bl; float* C; int kBeg, kEnd; };
struct TCArgs { TCZ z[3]; int ldc; };

// Stage (32KB): [0,16K) A rows 128x128B: [hi 64B | lo 64B]; [16K,32K) B same.
__global__ void __launch_bounds__(256,2) gemm_tc(TCArgs ga){
  extern __shared__ char smem[];
  uint32_t sb = smem_u32(smem);
  TCZ gz = ga.z[blockIdx.z];
  int mBase = blockIdx.y*128, nBase = blockIdx.x*128;
  int tid = threadIdx.x, wid = tid>>5, lid = tid&31;
  const int nc = (gz.kEnd - gz.kBeg)/KC;
  int wy = wid>>2, wx = wid&3, r4 = lid>>2, q4 = lid&3;

  float acc[4][4][4];
  #pragma unroll
  for (int mt=0;mt<4;mt++)
    #pragma unroll
    for (int nt=0;nt<4;nt++)
      #pragma unroll
      for (int c=0;c<4;c++) acc[mt][nt][c]=0.f;

  // async stage fill: 2048 x 16B cells, 8 per thread
  auto fill = [&](int s, int t){
    int k0 = gz.kBeg + t*KC;
    uint32_t base = sb + (uint32_t)s*32768u;
    #pragma unroll
    for (int i=0;i<8;i++){
      int c = tid + i*256;
      int arr = c>>10, cc = c&1023, row = cc>>3, u = cc&7, half = u>>2, uu = u&3;
      uint32_t off = (uint32_t)arr*16384u + SWZ128((uint32_t)(row*128 + half*64 + uu*16));
      const __nv_bfloat16* src;
      if (arr==0) src = (half ? gz.Al : gz.Ah) + (size_t)(mBase+row)*HH + k0 + uu*8;
      else        src = (half ? gz.Bl : gz.Bh) + (size_t)(nBase+row)*HH + k0 + uu*8;
      cpa16(base + off, src);
    }
    CP_COMMIT();
  };

  fill(0, 0);
  for (int t=0; t<nc; t++){
    if (t+1 < nc){ fill((t+1)&1, t+1); CP_WAIT1(); }
    else         { CP_WAIT0(); }
    __syncthreads();
    char* st = smem + (t&1)*32768;
    char* A = st; char* B = st + 16384;
    #pragma unroll
    for (int ks=0; ks<2; ks++){
      uint32_t cb = (uint32_t)(ks*32 + q4*4);
      uint32_t af[4][4];
      // pass 1: A-hi; Ah*Bh and Ah*Bl
      #pragma unroll
      for (int mt=0;mt<4;mt++){
        int row = wy*64 + mt*16 + r4;
        af[mt][0] = *(const uint32_t*)(A + SWZ128((uint32_t)(row*128 + cb)));
        af[mt][1] = *(const uint32_t*)(A + SWZ128((uint32_t)((row+8)*128 + cb)));
        af[mt][2] = *(const uint32_t*)(A + SWZ128((uint32_t)(row*128 + cb + 16)));
        af[mt][3] = *(const uint32_t*)(A + SWZ128((uint32_t)((row+8)*128 + cb + 16)));
      }
      #pragma unroll
      for (int nt=0;nt<4;nt++){
        int n0 = wx*32 + nt*8 + r4;
        uint32_t bh[2], bl[2];
        bh[0] = *(const uint32_t*)(B + SWZ128((uint32_t)(n0*128 + cb)));
        bh[1] = *(const uint32_t*)(B + SWZ128((uint32_t)(n0*128 + cb + 16)));
        bl[0] = *(const uint32_t*)(B + SWZ128((uint32_t)(n0*128 + 64 + cb)));
        bl[1] = *(const uint32_t*)(B + SWZ128((uint32_t)(n0*128 + 64 + cb + 16)));
        #pragma unroll
        for (int mt=0;mt<4;mt++){
          mma16816(acc[mt][nt], af[mt], bh);
          mma16816(acc[mt][nt], af[mt], bl);
        }
      }
      // pass 2: A-lo; Al*Bh
      #pragma unroll
      for (int mt=0;mt<4;mt++){
        int row = wy*64 + mt*16 + r4;
        af[mt][0] = *(const uint32_t*)(A + SWZ128((uint32_t)(row*128 + 64 + cb)));
        af[mt][1] = *(const uint32_t*)(A + SWZ128((uint32_t)((row+8)*128 + 64 + cb)));
        af[mt][2] = *(const uint32_t*)(A + SWZ128((uint32_t)(row*128 + 64 + cb + 16)));
        af[mt][3] = *(const uint32_t*)(A + SWZ128((uint32_t)((row+8)*128 + 64 + cb + 16)));
      }
      #pragma unroll
      for (int nt=0;nt<4;nt++){
        int n0 = wx*32 + nt*8 + r4;
        uint32_t bh[2];
        bh[0] = *(const uint32_t*)(B + SWZ128((uint32_t)(n0*128 + cb)));
        bh[1] = *(const uint32_t*)(B + SWZ128((uint32_t)(n0*128 + cb + 16)));
        #pragma unroll
        for (int mt=0;mt<4;mt++)
          mma16816(acc[mt][nt], af[mt], bh);
      }
    }
    __syncthreads();
  }
  #pragma unroll
  for (int mt=0;mt<4;mt++){
    #pragma unroll
    for (int nt=0;nt<4;nt++){
      int grow = mBase + wy*64 + mt*16 + r4;
      int gcol = nBase + wx*32 + nt*8 + q4*2;
      float* c0 = gz.C + (size_t)grow*ga.ldc + gcol;
      float* c1 = gz.C + (size_t)(grow+8)*ga.ldc + gcol;
      c0[0] = acc[mt][nt][0]; c0[1] = acc[mt][nt][1];
      c1[0] = acc[mt][nt][2]; c1[1] = acc[mt][nt][3];
    }
  }
}

// ---------------- small kernels ---------------------------------------------
__global__ void pe_kernel(){
  int pos = blockIdx.x;
  for (int d = threadIdx.x; d < HH; d += blockDim.x){
    double e = (double)(2*(d>>1)) / (double)HH;
    double ang = (double)pos / pow(10000.0, e);
    d_pe[pos*HH+d] = (float)((d&1) ? cos(ang) : sin(ang));
  }
}

__global__ void init_tokens(){
  int s = blockIdx.x, b = blockIdx.y;
  const float* src = nullptr;
  if (s < 2*THIST)       src = ((s&1) ? d_kb : d_qb) + (size_t)(b*THIST + (s>>1))*HH;
  else if (s == 2*THIST) src = d_vb + (size_t)b*HH;
  float* dst = d_tokens + (size_t)(b*S2+s)*HH;
  for (int d = threadIdx.x; d < HH; d += blockDim.x) dst[d] = src ? src[d] : 0.f;
}

__global__ void build_h(int step){
  int s = blockIdx.x, b = blockIdx.y;
  int pos_a = 2*THIST + 1 + 2*step;
  int L = pos_a + 1;
  size_t rb = (size_t)(b*S2+s)*HH;
  float* tok = d_tokens + rb;
  const float* ae = d_aemb + (size_t)(b*TACT + step)*HH;
  for (int d = threadIdx.x; d < HH; d += blockDim.x){
    float t;
    if (s == pos_a){ t = ae[d]; tok[d] = t; } else t = tok[d];
    float v = t + ((s < L) ? d_pe[s*HH+d] : 0.f);
    d_h[rb+d] = v;
    __nv_bfloat16 h, l; split_bf(v, h, l);
    d_h_hi[rb+d] = h; d_h_lo[rb+d] = l;
  }
}

struct GemmZ { const float* A; const float* W; float* C; int kBeg, kEnd, M, lda; };
struct GemmArgs { GemmZ z[4]; int ldc; int act; };

__global__ void __launch_bounds__(256,2) gemm_kernel(GemmArgs ga){
  GemmZ gz = ga.z[blockIdx.z];
  int mBase = blockIdx.y*128;
  if (mBase >= gz.M) return;
  int nBase = blockIdx.x*128;
  int tid = threadIdx.x, tx = tid&15, ty = tid>>4;
  __shared__ float As[2][16][128];
  __shared__ float Bs[2][16][128];
  int arow[2], ak4[2], brow[2], bc4[2]; bool aok[2];
  #pragma unroll
  for (int i=0;i<2;i++){
    int f = tid + i*256;
    arow[i]=f>>2; ak4[i]=f&3; aok[i]=(mBase+arow[i])<gz.M;
    brow[i]=f>>5; bc4[i]=f&31;
  }
  int nt = (gz.kEnd - gz.kBeg)>>4;
  float4 av[2], bv[2];
  {
    int k0 = gz.kBeg;
    #pragma unroll
    for (int i=0;i<2;i++){
      av[i] = aok[i] ? *(const float4*)(gz.A + (size_t)(mBase+arow[i])*gz.lda + k0 + ak4[i]*4)
                     : make_float4(0.f,0.f,0.f,0.f);
      bv[i] = *(const float4*)(gz.W + (size_t)(k0+brow[i])*HH + nBase + bc4[i]*4);
    }
    #pragma unroll
    for (int i=0;i<2;i++){
      As[0][ak4[i]*4+0][arow[i]]=av[i].x; As[0][ak4[i]*4+1][arow[i]]=av[i].y;
      As[0][ak4[i]*4+2][arow[i]]=av[i].z; As[0][ak4[i]*4+3][arow[i]]=av[i].w;
      *(float4*)&Bs[0][brow[i]][bc4[i]*4] = bv[i];
    }
  }
  __syncthreads();
  float acc[8][8];
  #pragma unroll
  for (int r=0;r<8;r++)
    #pragma unroll
    for (int c=0;c<8;c++) acc[r][c]=0.f;
  int buf=0;
  for (int t=0;t<nt;t++){
    if (t+1<nt){
      int k0 = gz.kBeg + (t+1)*16;
      #pragma unroll
      for (int i=0;i<2;i++){
        av[i] = aok[i] ? *(const float4*)(gz.A + (size_t)(mBase+arow[i])*gz.lda + k0 + ak4[i]*4)
                       : make_float4(0.f,0.f,0.f,0.f);
        bv[i] = *(const float4*)(gz.W + (size_t)(k0+brow[i])*HH + nBase + bc4[i]*4);
      }
    }
    #pragma unroll
    for (int kk=0;kk<16;kk++){
      float4 a0=*(const float4*)&As[buf][kk][ty*8];
      float4 a1=*(const float4*)&As[buf][kk][ty*8+4];
      float4 b0=*(const float4*)&Bs[buf][kk][tx*8];
      float4 b1=*(const float4*)&Bs[buf][kk][tx*8+4];
      float a[8]={a0.x,a0.y,a0.z,a0.w,a1.x,a1.y,a1.z,a1.w};
      float bb[8]={b0.x,b0.y,b0.z,b0.w,b1.x,b1.y,b1.z,b1.w};
      #pragma unroll
      for (int r=0;r<8;r++)
        #pragma unroll
        for (int c=0;c<8;c++) acc[r][c]=fmaf(a[r],bb[c],acc[r][c]);
    }
    if (t+1<nt){
      buf^=1;
      #pragma unroll
      for (int i=0;i<2;i++){
        As[buf][ak4[i]*4+0][arow[i]]=av[i].x; As[buf][ak4[i]*4+1][arow[i]]=av[i].y;
        As[buf][ak4[i]*4+2][arow[i]]=av[i].z; As[buf][ak4[i]*4+3][arow[i]]=av[i].w;
        *(float4*)&Bs[buf][brow[i]][bc4[i]*4]=bv[i];
      }
      __syncthreads();
    }
  }
  #pragma unroll
  for (int r=0;r<8;r++){
    int grow = mBase + ty*8 + r;
    if (grow < gz.M){
      float* cp = gz.C + (size_t)grow*ga.ldc + nBase + tx*8;
      #pragma unroll
      for (int c=0;c<8;c++){
        float v = acc[r][c];
        if (ga.act) v = v>0.f ? v : 0.f;
        cp[c] = v;
      }
    }
  }
}

__global__ void attn_kernel(int L){
  __shared__ float Qs[S2][DHEAD];
  __shared__ float Ks[S2][DHEAD+1];
  __shared__ float Vs[S2][DHEAD];
  __shared__ float Ps[S2][S2+1];
  int bh = blockIdx.x, b = bh>>4, hd = bh&15, tid = threadIdx.x;
  const float* qb = d_qb + (size_t)(b*S2)*HH + hd*DHEAD;
  const float* kb = d_kb + (size_t)(b*S2)*HH + hd*DHEAD;
  const float* vb = d_vb + (size_t)(b*S2)*HH + hd*DHEAD;
  for (int i = tid; i < S2*DHEAD; i += blockDim.x){
    int s=i>>6, d=i&63;
    Qs[s][d]=qb[(size_t)s*HH+d]; Ks[s][d]=kb[(size_t)s*HH+d]; Vs[s][d]=vb[(size_t)s*HH+d];
  }
  __syncthreads();
  for (int i = tid; i < S2*S2; i += blockDim.x){
    int q=i>>5, k=i&31;
    float sc=0.f;
    #pragma unroll
    for (int d=0;d<DHEAD;d++) sc += Qs[q][d]*Ks[k][d];
    sc *= 0.125f;
    if (!(q<L && k<L)) sc = -1e20f;
    Ps[q][k]=sc;
  }
  __syncthreads();
  if (tid < S2){
    int q = tid;
    if (q >= L){ for (int k=0;k<S2;k++) Ps[q][k]=0.f; }
    else {
      float mx=-3.4e38f;
      for (int k=0;k<S2;k++) mx = fmaxf(mx, Ps[q][k]);
      float sum=0.f;
      for (int k=0;k<S2;k++){ float e=expf(Ps[q][k]-mx); Ps[q][k]=e; sum+=e; }
      float inv=1.f/sum;
      for (int k=0;k<S2;k++) Ps[q][k] = (k<L) ? Ps[q][k]*inv : 0.f;
    }
  }
  __syncthreads();
  for (int i = tid; i < S2*DHEAD; i += blockDim.x){
    int q=i>>6, d=i&63;
    float o=0.f;
    #pragma unroll
    for (int k=0;k<S2;k++) o += Ps[q][k]*Vs[k][d];
    size_t off = (size_t)(b*S2+q)*HH + hd*DHEAD + d;
    __nv_bfloat16 h, l; split_bf(o, h, l);
    d_ctx_hi[off] = h; d_ctx_lo[off] = l;
  }
}

__device__ __forceinline__ float block_sum(float v){
  __shared__ float red[32];
  int lane=threadIdx.x&31, wid=threadIdx.x>>5;
  #pragma unroll
  for (int o=16;o>0;o>>=1) v += __shfl_down_sync(0xffffffffu, v, o);
  if (lane==0) red[wid]=v;
  __syncthreads();
  float r = (threadIdx.x < (blockDim.x>>5)) ? red[threadIdx.x] : 0.f;
  if (wid==0){
    #pragma unroll
    for (int o=16;o>0;o>>=1) r += __shfl_down_sync(0xffffffffu, r, o);
    if (lane==0) red[0]=r;
  }
  __syncthreads();
  float out = red[0];
  __syncthreads();
  return out;
}

__global__ void ln_kernel(const float* __restrict__ x, const float* __restrict__ p0,
                          const float* __restrict__ p1, const float* __restrict__ g,
                          const float* __restrict__ bia, float* out,
                          __nv_bfloat16* out_hi, __nv_bfloat16* out_lo,
                          __nv_bfloat16* out2_hi, __nv_bfloat16* out2_lo){
  int row = blockIdx.x, tid = threadIdx.x;
  float v[4]; float s=0.f;
  #pragma unroll
  for (int i=0;i<4;i++){
    size_t off = (size_t)row*HH + tid + i*256;
    float t = x[off]+p0[off]+p1[off];
    v[i]=t; s+=t;
  }
  float mean = block_sum(s)*(1.f/HH);
  float s2=0.f;
  #pragma unroll
  for (int i=0;i<4;i++){ float dd=v[i]-mean; s2+=dd*dd; }
  float inv = 1.f/sqrtf(block_sum(s2)*(1.f/HH) + 1e-5f);
  #pragma unroll
  for (int i=0;i<4;i++){
    int d = tid + i*256;
    size_t off = (size_t)row*HH + d;
    float y = (v[i]-mean)*inv*g[d] + bia[d];
    out[off]=y;
    __nv_bfloat16 h, l; split_bf(y, h, l);
    out_hi[off]=h; out_lo[off]=l;
    if (out2_hi){ out2_hi[off]=h; out2_lo[off]=l; }
  }
}

__global__ void wr_kernel(const float* __restrict__ Wr, float* out, int step){
  int b = blockIdx.x;
  float s=0.f;
  const float* hf = d_h + (size_t)b*S2*HH;
  for (int x = threadIdx.x; x < S2*HH; x += blockDim.x) s += hf[x]*Wr[x];
  s = block_sum(s);
  if (threadIdx.x==0) out[b*TACT+step] = 1.f/(1.f+expf(-s));
}

__global__ void wso_part(const float* __restrict__ Wso){
  int nb = blockIdx.x, sp = blockIdx.y, tid = threadIdx.x;
  int tx = tid&63, tg = tid>>6;
  __shared__ float Asm[32][33];
  __shared__ float Wsm[32][64];
  float acc[8];
  #pragma unroll
  for (int r=0;r<8;r++) acc[r]=0.f;
  const int kLen = (S2*HH)/WSOSPLIT, k0 = sp*kLen;
  for (int kc=0; kc<kLen; kc+=32){
    for (int i=tid; i<32*32; i+=256){
      int bq=i>>5, kk=i&31;
      Asm[bq][kk] = d_h[(size_t)bq*S2*HH + k0+kc+kk];
    }
    for (int i=tid; i<32*64; i+=256){
      int kk=i>>6, cc=i&63;
      Wsm[kk][cc] = Wso[(size_t)(k0+kc+kk)*HINN + nb*64 + cc];
    }
    __syncthreads();
    #pragma unroll
    for (int kk=0;kk<32;kk++){
      float w = Wsm[kk][tx];
      #pragma unroll
      for (int r=0;r<8;r++) acc[r] = fmaf(Asm[tg*8+r][kk], w, acc[r]);
    }
    __syncthreads();
  }
  #pragma unroll
  for (int r=0;r<8;r++)
    d_wsop[(size_t)sp*BB*HINN + (size_t)(tg*8+r)*HINN + nb*64 + tx] = acc[r];
}

__global__ void wso_reduce(float* out, int step){
  int b = blockIdx.x, n = threadIdx.x;
  float s=0.f;
  #pragma unroll
  for (int sp=0;sp<WSOSPLIT;sp++) s += d_wsop[(size_t)sp*BB*HINN + (size_t)b*HINN + n];
  s = fmaxf(s, 0.f);
  d_snew[b*HINN+n] = s;
  out[BB*TACT + (size_t)(b*TACT+step)*HINN + n] = s;
}

static void* sym(const void* s){ void* p = nullptr; cudaGetSymbolAddress(&p, s); return p; }

extern "C" void kernel_launch(void* const* d_in, const int* in_sizes, int n_in,
                              void* d_out, int out_size){
  (void)in_sizes; (void)n_in; (void)out_size;
  const float* hist_s=(const float*)d_in[0];
  const float* hist_a=(const float*)d_in[1];
  const float* s_in  =(const float*)d_in[2];
  const float* a_list=(const float*)d_in[3];
  const float* Ws =(const float*)d_in[4];
  const float* Wa =(const float*)d_in[5];
  const float* Wq =(const float*)d_in[6];
  const float* Wk =(const float*)d_in[7];
  const float* Wv =(const float*)d_in[8];
  const float* Wo =(const float*)d_in[9];
  const float* Wfc=(const float*)d_in[10];
  const float* ln1g=(const float*)d_in[11];
  const float* ln1b=(const float*)d_in[12];
  const float* ln2g=(const float*)d_in[13];
  const float* ln2b=(const float*)d_in[14];
  const float* Wr =(const float*)d_in[15];
  const float* Wso=(const float*)d_in[16];
  float* out = (float*)d_out;

  float* ph   =(float*)sym(d_h);
  float* pq   =(float*)sym(d_qb);
  float* pk   =(float*)sym(d_kb);
  float* pv   =(float*)sym(d_vb);
  float* pp0  =(float*)sym(d_p0);
  float* pp1  =(float*)sym(d_p1);
  float* pae  =(float*)sym(d_aemb);
  float* psn  =(float*)sym(d_snew);
  float* ptok =(float*)sym(d_tokens);
  __nv_bfloat16* phh=(__nv_bfloat16*)sym(d_h_hi);
  __nv_bfloat16* phl=(__nv_bfloat16*)sym(d_h_lo);
  __nv_bfloat16* pch=(__nv_bfloat16*)sym(d_ctx_hi);
  __nv_bfloat16* pcl=(__nv_bfloat16*)sym(d_ctx_lo);
  __nv_bfloat16* pvh=(__nv_bfloat16*)sym(d_prev_hi);
  __nv_bfloat16* pvl=(__nv_bfloat16*)sym(d_prev_lo);
  __nv_bfloat16* pwh=(__nv_bfloat16*)sym(d_wt_hi);
  __nv_bfloat16* pwl=(__nv_bfloat16*)sym(d_wt_lo);

  cudaFuncSetAttribute(gemm_tc, cudaFuncAttributeMaxDynamicSharedMemorySize, TC_SMEM);

  pe_kernel<<<S2,256>>>();
  wcvt_kernel<<<dim3(32,32,NW),dim3(32,8)>>>(Wq, Wk, Wv, Wo, Wfc);

  {
    GemmArgs ga{};
    ga.ldc=HH; ga.act=1;
    ga.z[0]=GemmZ{hist_s, Ws, pq, 0, HINN, BB*THIST, HINN};
    ga.z[1]=GemmZ{hist_a, Wa, pk, 0, 64,   BB*THIST, 64};
    ga.z[2]=GemmZ{s_in,   Ws, pv, 0, HINN, BB,       HINN};
    ga.z[3]=GemmZ{a_list, Wa, pae,0, 64,   BB*TACT,  64};
    gemm_kernel<<<dim3(8,2,4),256>>>(ga);
  }
  init_tokens<<<dim3(S2,BB),256>>>();

  const size_t WSZ = (size_t)HH*HH;
  const size_t PSZ = (size_t)MR*HH;
  for (int i=0;i<TACT;i++){
    int L = 2*THIST + 2 + 2*i;
    build_h<<<dim3(S2,BB),256>>>(i);
    for (int j=0;j<NLAY;j++){
      const __nv_bfloat16* qkh = (i==0) ? phh : (pvh + (size_t)j*PSZ);
      const __nv_bfloat16* qkl = (i==0) ? phl : (pvl + (size_t)j*PSZ);
      {
        TCArgs ga{};
        ga.ldc=HH;
        ga.z[0]=TCZ{qkh, qkl, pwh + (size_t)(0*4+j)*WSZ, pwl + (size_t)(0*4+j)*WSZ, pq, 0, HH};
        ga.z[1]=TCZ{qkh, qkl, pwh + (size_t)(1*4+j)*WSZ, pwl + (size_t)(1*4+j)*WSZ, pk, 0, HH};
        ga.z[2]=TCZ{phh, phl, pwh + (size_t)(2*4+j)*WSZ, pwl + (size_t)(2*4+j)*WSZ, pv, 0, HH};
        gemm_tc<<<dim3(8,8,3),256,TC_SMEM>>>(ga);
      }
      attn_kernel<<<BB*16,256>>>(L);
      {
        TCArgs ga{};
        ga.ldc=HH;
        ga.z[0]=TCZ{pch, pcl, pwh + (size_t)(3*4+j)*WSZ, pwl + (size_t)(3*4+j)*WSZ, pp0, 0,    HH/2};
        ga.z[1]=TCZ{pch, pcl, pwh + (size_t)(3*4+j)*WSZ, pwl + (size_t)(3*4+j)*WSZ, pp1, HH/2, HH};
        gemm_tc<<<dim3(8,8,2),256,TC_SMEM>>>(ga);
      }
      ln_kernel<<<MR,256>>>(ph, pp0, pp1, ln1g+(size_t)j*HH, ln1b+(size_t)j*HH,
                            ph, phh, phl, nullptr, nullptr);
      {
        TCArgs ga{};
        ga.ldc=HH;
        ga.z[0]=TCZ{phh, phl, pwh + (size_t)(4*4+j)*WSZ, pwl + (size_t)(4*4+j)*WSZ, pp0, 0,    HH/2};
        ga.z[1]=TCZ{phh, phl, pwh + (size_t)(4*4+j)*WSZ, pwl + (size_t)(4*4+j)*WSZ, pp1, HH/2, HH};
        gemm_tc<<<dim3(8,8,2),256,TC_SMEM>>>(ga);
      }
      ln_kernel<<<MR,256>>>(ph, pp0, pp1, ln2g+(size_t)j*HH, ln2b+(size_t)j*HH,
                            ph, phh, phl, pvh + (size_t)j*PSZ, pvl + (size_t)j*PSZ);
    }
    wr_kernel<<<BB,1024>>>(Wr, out, i);
    wso_part<<<dim3(8,WSOSPLIT),256>>>(Wso);
    wso_reduce<<<BB,HINN>>>(out, i);
    if (i+1 < TACT){
      int pos_s = 2*THIST + 2 + 2*i;
      GemmArgs ga{};
      ga.ldc=S2*HH; ga.act=1;
      ga.z[0]=GemmZ{psn, Ws, ptok + (size_t)pos_s*HH, 0, HINN, BB, HINN};
      gemm_kernel<<<dim3(8,1,1),256>>>(ga);
    }
  }
}

// round 15
// speedup vs baseline: 2.4496x; 1.0453x over previous
#include <cuda_runtime.h>
#include <cuda_bf16.h>
#include <stdint.h>
#include <math.h>

#define BB 32
#define S2 32
#define HH 1024
#define DHEAD 64
#define NLAY 4
#define THIST 8
#define TACT 8
#define HINN 512
#define MR (BB*S2)
#define WSOSPLIT 16
#define NW 20
#define KC 32
#define TC_SMEM 98304

__device__ float d_pe[S2*HH];
__device__ float d_tokens[MR*HH];
__device__ float d_h[MR*HH];
__device__ float d_qb[MR*HH];
__device__ float d_kb[MR*HH];
__device__ float d_vb[MR*HH];
__device__ float d_q2[MR*HH];
__device__ float d_k2[MR*HH];
__device__ float d_v2[MR*HH];
__device__ float d_p0[MR*HH];
__device__ float d_p1[MR*HH];
__device__ float d_p2[MR*HH];
__device__ float d_p3[MR*HH];
__device__ float d_aemb[BB*TACT*HH];
__device__ float d_snew[BB*HINN];
__device__ float d_wsop[WSOSPLIT*BB*HINN];
__device__ __nv_bfloat16 d_h_hi[MR*HH];
__device__ __nv_bfloat16 d_h_lo[MR*HH];
__device__ __nv_bfloat16 d_ctx_hi[MR*HH];
__device__ __nv_bfloat16 d_ctx_lo[MR*HH];
__device__ __nv_bfloat16 d_prev_hi[NLAY][MR*HH];
__device__ __nv_bfloat16 d_prev_lo[NLAY][MR*HH];
__device__ __nv_bfloat16 d_wt_hi[(size_t)NW*HH*HH];
__device__ __nv_bfloat16 d_wt_lo[(size_t)NW*HH*HH];

// ---------------- helpers ---------------------------------------------------
#define SWZ128(o) ((o) ^ (((o) >> 3) & 0x70))

__device__ __forceinline__ uint32_t smem_u32(const void* p){
  uint32_t a;
  asm("{ .reg .u64 t; cvta.to.shared.u64 t, %1; cvt.u32.u64 %0, t; }" : "=r"(a) : "l"(p));
  return a;
}
__device__ __forceinline__ void cpa16(uint32_t d, const void* s){
  asm volatile("cp.async.cg.shared.global [%0], [%1], 16;" :: "r"(d), "l"(s));
}
#define CP_COMMIT() asm volatile("cp.async.commit_group;" ::: "memory")
#define CP_WAIT1()  asm volatile("cp.async.wait_group 1;" ::: "memory")
#define CP_WAIT0()  asm volatile("cp.async.wait_group 0;" ::: "memory")

__device__ __forceinline__ void split_bf(float v, __nv_bfloat16& h, __nv_bfloat16& l){
  h = __float2bfloat16(v);
  l = __float2bfloat16(v - __bfloat162float(h));
}

__device__ __forceinline__ void mma16816(float* c, const uint32_t* a, const uint32_t* b){
  asm volatile("mma.sync.aligned.m16n8k16.row.col.f32.bf16.bf16.f32 "
    "{%0,%1,%2,%3}, {%4,%5,%6,%7}, {%8,%9}, {%0,%1,%2,%3};"
    : "+f"(c[0]),"+f"(c[1]),"+f"(c[2]),"+f"(c[3])
    : "r"(a[0]),"r"(a[1]),"r"(a[2]),"r"(a[3]), "r"(b[0]),"r"(b[1]));
}

// ---------------- weight transpose + hi/lo split ----------------------------
__global__ void wcvt_kernel(const float* __restrict__ Wq, const float* __restrict__ Wk,
                            const float* __restrict__ Wv, const float* __restrict__ Wo,
                            const float* __restrict__ Wfc){
  __shared__ float tile[32][33];
  int z = blockIdx.z;
  const float* src;
  if (z < 4)       src = Wq  + (size_t)z*HH*HH;
  else if (z < 8)  src = Wk  + (size_t)(z-4)*HH*HH;
  else if (z < 12) src = Wv  + (size_t)(z-8)*HH*HH;
  else if (z < 16) src = Wo  + (size_t)(z-12)*HH*HH;
  else             src = Wfc + (size_t)(z-16)*HH*HH;
  __nv_bfloat16* dh = d_wt_hi + (size_t)z*HH*HH;
  __nv_bfloat16* dl = d_wt_lo + (size_t)z*HH*HH;
  int n0 = blockIdx.x*32, k0 = blockIdx.y*32;
  int tx = threadIdx.x, ty = threadIdx.y;
  #pragma unroll
  for (int i=0;i<4;i++)
    tile[ty+i*8][tx] = src[(size_t)(k0+ty+i*8)*HH + n0 + tx];
  __syncthreads();
  #pragma unroll
  for (int i=0;i<4;i++){
    float v = tile[tx][ty+i*8];
    __nv_bfloat16 h, l; split_bf(v, h, l);
    size_t o = (size_t)(n0+ty+i*8)*HH + k0 + tx;
    dh[o] = h; dl[o] = l;
  }
}

// ---------------- tensor-core GEMM (cp.async 3-stage, 8 warps) --------------
struct TCZ { const __nv_bfloat16 *Ah, *Al, *Bh, *Bl; float* C; int kBeg, kEnd; };
struct TCArgs { TCZ z[6]; int ldc; };

// Stage (32KB): [0,16K) A rows 128x128B: [hi 64B | lo 64B]; [16K,32K) B same.
__global__ void __launch_bounds__(256,2) gemm_tc(TCArgs ga){
  extern __shared__ char smem[];
  uint32_t sb = smem_u32(smem);
  TCZ gz = ga.z[blockIdx.z];
  int mBase = blockIdx.y*128, nBase = blockIdx.x*128;
  int tid = threadIdx.x, wid = tid>>5, lid = tid&31;
  const int nc = (gz.kEnd - gz.kBeg)/KC;
  int wy = wid>>2, wx = wid&3, r4 = lid>>2, q4 = lid&3;

  float acc[4][4][4];
  #pragma unroll
  for (int mt=0;mt<4;mt++)
    #pragma unroll
    for (int nt=0;nt<4;nt++)
      #pragma unroll
      for (int c=0;c<4;c++) acc[mt][nt][c]=0.f;

  auto fill = [&](int s, int t){
    int k0 = gz.kBeg + t*KC;
    uint32_t base = sb + (uint32_t)s*32768u;
    #pragma unroll
    for (int i=0;i<8;i++){
      int c = tid + i*256;
      int arr = c>>10, cc = c&1023, row = cc>>3, u = cc&7, half = u>>2, uu = u&3;
      uint32_t off = (uint32_t)arr*16384u + SWZ128((uint32_t)(row*128 + half*64 + uu*16));
      const __nv_bfloat16* src;
      if (arr==0) src = (half ? gz.Al : gz.Ah) + (size_t)(mBase+row)*HH + k0 + uu*8;
      else        src = (half ? gz.Bl : gz.Bh) + (size_t)(nBase+row)*HH + k0 + uu*8;
      cpa16(base + off, src);
    }
    CP_COMMIT();
  };

  fill(0, 0);
  if (nc > 1) fill(1, 1);
  for (int t=0; t<nc; t++){
    if (t+1 < nc) CP_WAIT1(); else CP_WAIT0();
    __syncthreads();
    if (t+2 < nc) fill((t+2)%3, t+2);
    char* st = smem + (t%3)*32768;
    char* A = st; char* B = st + 16384;
    #pragma unroll
    for (int ks=0; ks<2; ks++){
      uint32_t cb = (uint32_t)(ks*32 + q4*4);
      uint32_t af[4][4];
      // pass 1: A-hi; Ah*Bh and Ah*Bl
      #pragma unroll
      for (int mt=0;mt<4;mt++){
        int row = wy*64 + mt*16 + r4;
        af[mt][0] = *(const uint32_t*)(A + SWZ128((uint32_t)(row*128 + cb)));
        af[mt][1] = *(const uint32_t*)(A + SWZ128((uint32_t)((row+8)*128 + cb)));
        af[mt][2] = *(const uint32_t*)(A + SWZ128((uint32_t)(row*128 + cb + 16)));
        af[mt][3] = *(const uint32_t*)(A + SWZ128((uint32_t)((row+8)*128 + cb + 16)));
      }
      #pragma unroll
      for (int nt=0;nt<4;nt++){
        int n0 = wx*32 + nt*8 + r4;
        uint32_t bh[2], bl[2];
        bh[0] = *(const uint32_t*)(B + SWZ128((uint32_t)(n0*128 + cb)));
        bh[1] = *(const uint32_t*)(B + SWZ128((uint32_t)(n0*128 + cb + 16)));
        bl[0] = *(const uint32_t*)(B + SWZ128((uint32_t)(n0*128 + 64 + cb)));
        bl[1] = *(const uint32_t*)(B + SWZ128((uint32_t)(n0*128 + 64 + cb + 16)));
        #pragma unroll
        for (int mt=0;mt<4;mt++){
          mma16816(acc[mt][nt], af[mt], bh);
          mma16816(acc[mt][nt], af[mt], bl);
        }
      }
      // pass 2: A-lo; Al*Bh
      #pragma unroll
      for (int mt=0;mt<4;mt++){
        int row = wy*64 + mt*16 + r4;
        af[mt][0] = *(const uint32_t*)(A + SWZ128((uint32_t)(row*128 + 64 + cb)));
        af[mt][1] = *(const uint32_t*)(A + SWZ128((uint32_t)((row+8)*128 + 64 + cb)));
        af[mt][2] = *(const uint32_t*)(A + SWZ128((uint32_t)(row*128 + 64 + cb + 16)));
        af[mt][3] = *(const uint32_t*)(A + SWZ128((uint32_t)((row+8)*128 + 64 + cb + 16)));
      }
      #pragma unroll
      for (int nt=0;nt<4;nt++){
        int n0 = wx*32 + nt*8 + r4;
        uint32_t bh[2];
        bh[0] = *(const uint32_t*)(B + SWZ128((uint32_t)(n0*128 + cb)));
        bh[1] = *(const uint32_t*)(B + SWZ128((uint32_t)(n0*128 + cb + 16)));
        #pragma unroll
        for (int mt=0;mt<4;mt++)
          mma16816(acc[mt][nt], af[mt], bh);
      }
    }
    __syncthreads();
  }
  #pragma unroll
  for (int mt=0;mt<4;mt++){
    #pragma unroll
    for (int nt=0;nt<4;nt++){
      int grow = mBase + wy*64 + mt*16 + r4;
      int gcol = nBase + wx*32 + nt*8 + q4*2;
      float* c0 = gz.C + (size_t)grow*ga.ldc + gcol;
      float* c1 = gz.C + (size_t)(grow+8)*ga.ldc + gcol;
      c0[0] = acc[mt][nt][0]; c0[1] = acc[mt][nt][1];
      c1[0] = acc[mt][nt][2]; c1[1] = acc[mt][nt][3];
    }
  }
}

// ---------------- small kernels ---------------------------------------------
__global__ void pe_kernel(){
  int pos = blockIdx.x;
  for (int d = threadIdx.x; d < HH; d += blockDim.x){
    double e = (double)(2*(d>>1)) / (double)HH;
    double ang = (double)pos / pow(10000.0, e);
    d_pe[pos*HH+d] = (float)((d&1) ? cos(ang) : sin(ang));
  }
}

__global__ void init_tokens(){
  int s = blockIdx.x, b = blockIdx.y;
  const float* src = nullptr;
  if (s < 2*THIST)       src = ((s&1) ? d_kb : d_qb) + (size_t)(b*THIST + (s>>1))*HH;
  else if (s == 2*THIST) src = d_vb + (size_t)b*HH;
  float* dst = d_tokens + (size_t)(b*S2+s)*HH;
  for (int d = threadIdx.x; d < HH; d += blockDim.x) dst[d] = src ? src[d] : 0.f;
}

__global__ void build_h(int step){
  int s = blockIdx.x, b = blockIdx.y;
  int pos_a = 2*THIST + 1 + 2*step;
  int L = pos_a + 1;
  size_t rb = (size_t)(b*S2+s)*HH;
  float* tok = d_tokens + rb;
  const float* ae = d_aemb + (size_t)(b*TACT + step)*HH;
  for (int d = threadIdx.x; d < HH; d += blockDim.x){
    float t;
    if (s == pos_a){ t = ae[d]; tok[d] = t; } else t = tok[d];
    float v = t + ((s < L) ? d_pe[s*HH+d] : 0.f);
    d_h[rb+d] = v;
    __nv_bfloat16 h, l; split_bf(v, h, l);
    d_h_hi[rb+d] = h; d_h_lo[rb+d] = l;
  }
}

struct GemmZ { const float* A; const float* W; float* C; int kBeg, kEnd, M, lda; };
struct GemmArgs { GemmZ z[4]; int ldc; int act; };

__global__ void __launch_bounds__(256,2) gemm_kernel(GemmArgs ga){
  GemmZ gz = ga.z[blockIdx.z];
  int mBase = blockIdx.y*128;
  if (mBase >= gz.M) return;
  int nBase = blockIdx.x*128;
  int tid = threadIdx.x, tx = tid&15, ty = tid>>4;
  __shared__ float As[2][16][128];
  __shared__ float Bs[2][16][128];
  int arow[2], ak4[2], brow[2], bc4[2]; bool aok[2];
  #pragma unroll
  for (int i=0;i<2;i++){
    int f = tid + i*256;
    arow[i]=f>>2; ak4[i]=f&3; aok[i]=(mBase+arow[i])<gz.M;
    brow[i]=f>>5; bc4[i]=f&31;
  }
  int nt = (gz.kEnd - gz.kBeg)>>4;
  float4 av[2], bv[2];
  {
    int k0 = gz.kBeg;
    #pragma unroll
    for (int i=0;i<2;i++){
      av[i] = aok[i] ? *(const float4*)(gz.A + (size_t)(mBase+arow[i])*gz.lda + k0 + ak4[i]*4)
                     : make_float4(0.f,0.f,0.f,0.f);
      bv[i] = *(const float4*)(gz.W + (size_t)(k0+brow[i])*HH + nBase + bc4[i]*4);
    }
    #pragma unroll
    for (int i=0;i<2;i++){
      As[0][ak4[i]*4+0][arow[i]]=av[i].x; As[0][ak4[i]*4+1][arow[i]]=av[i].y;
      As[0][ak4[i]*4+2][arow[i]]=av[i].z; As[0][ak4[i]*4+3][arow[i]]=av[i].w;
      *(float4*)&Bs[0][brow[i]][bc4[i]*4] = bv[i];
    }
  }
  __syncthreads();
  float acc[8][8];
  #pragma unroll
  for (int r=0;r<8;r++)
    #pragma unroll
    for (int c=0;c<8;c++) acc[r][c]=0.f;
  int buf=0;
  for (int t=0;t<nt;t++){
    if (t+1<nt){
      int k0 = gz.kBeg + (t+1)*16;
      #pragma unroll
      for (int i=0;i<2;i++){
        av[i] = aok[i] ? *(const float4*)(gz.A + (size_t)(mBase+arow[i])*gz.lda + k0 + ak4[i]*4)
                       : make_float4(0.f,0.f,0.f,0.f);
        bv[i] = *(const float4*)(gz.W + (size_t)(k0+brow[i])*HH + nBase + bc4[i]*4);
      }
    }
    #pragma unroll
    for (int kk=0;kk<16;kk++){
      float4 a0=*(const float4*)&As[buf][kk][ty*8];
      float4 a1=*(const float4*)&As[buf][kk][ty*8+4];
      float4 b0=*(const float4*)&Bs[buf][kk][tx*8];
      float4 b1=*(const float4*)&Bs[buf][kk][tx*8+4];
      float a[8]={a0.x,a0.y,a0.z,a0.w,a1.x,a1.y,a1.z,a1.w};
      float bb[8]={b0.x,b0.y,b0.z,b0.w,b1.x,b1.y,b1.z,b1.w};
      #pragma unroll
      for (int r=0;r<8;r++)
        #pragma unroll
        for (int c=0;c<8;c++) acc[r][c]=fmaf(a[r],bb[c],acc[r][c]);
    }
    if (t+1<nt){
      buf^=1;
      #pragma unroll
      for (int i=0;i<2;i++){
        As[buf][ak4[i]*4+0][arow[i]]=av[i].x; As[buf][ak4[i]*4+1][arow[i]]=av[i].y;
        As[buf][ak4[i]*4+2][arow[i]]=av[i].z; As[buf][ak4[i]*4+3][arow[i]]=av[i].w;
        *(float4*)&Bs[buf][brow[i]][bc4[i]*4]=bv[i];
      }
      __syncthreads();
    }
  }
  #pragma unroll
  for (int r=0;r<8;r++){
    int grow = mBase + ty*8 + r;
    if (grow < gz.M){
      float* cp = gz.C + (size_t)grow*ga.ldc + nBase + tx*8;
      #pragma unroll
      for (int c=0;c<8;c++){
        float v = acc[r][c];
        if (ga.act) v = v>0.f ? v : 0.f;
        cp[c] = v;
      }
    }
  }
}

__global__ void attn_kernel(int L){
  __shared__ float Qs[S2][DHEAD];
  __shared__ float Ks[S2][DHEAD+1];
  __shared__ float Vs[S2][DHEAD];
  __shared__ float Ps[S2][S2+1];
  int bh = blockIdx.x, b = bh>>4, hd = bh&15, tid = threadIdx.x;
  size_t base = (size_t)(b*S2)*HH + hd*DHEAD;
  for (int i = tid; i < S2*DHEAD; i += blockDim.x){
    int s=i>>6, d=i&63;
    size_t o = base + (size_t)s*HH + d;
    Qs[s][d]=d_qb[o]+d_q2[o]; Ks[s][d]=d_kb[o]+d_k2[o]; Vs[s][d]=d_vb[o]+d_v2[o];
  }
  __syncthreads();
  for (int i = tid; i < S2*S2; i += blockDim.x){
    int q=i>>5, k=i&31;
    float sc=0.f;
    #pragma unroll
    for (int d=0;d<DHEAD;d++) sc += Qs[q][d]*Ks[k][d];
    sc *= 0.125f;
    if (!(q<L && k<L)) sc = -1e20f;
    Ps[q][k]=sc;
  }
  __syncthreads();
  if (tid < S2){
    int q = tid;
    if (q >= L){ for (int k=0;k<S2;k++) Ps[q][k]=0.f; }
    else {
      float mx=-3.4e38f;
      for (int k=0;k<S2;k++) mx = fmaxf(mx, Ps[q][k]);
      float sum=0.f;
      for (int k=0;k<S2;k++){ float e=expf(Ps[q][k]-mx); Ps[q][k]=e; sum+=e; }
      float inv=1.f/sum;
      for (int k=0;k<S2;k++) Ps[q][k] = (k<L) ? Ps[q][k]*inv : 0.f;
    }
  }
  __syncthreads();
  for (int i = tid; i < S2*DHEAD; i += blockDim.x){
    int q=i>>6, d=i&63;
    float o=0.f;
    #pragma unroll
    for (int k=0;k<S2;k++) o += Ps[q][k]*Vs[k][d];
    size_t off = (size_t)(b*S2+q)*HH + hd*DHEAD + d;
    __nv_bfloat16 h, l; split_bf(o, h, l);
    d_ctx_hi[off] = h; d_ctx_lo[off] = l;
  }
}

__device__ __forceinline__ float block_sum(float v){
  __shared__ float red[32];
  int lane=threadIdx.x&31, wid=threadIdx.x>>5;
  #pragma unroll
  for (int o=16;o>0;o>>=1) v += __shfl_down_sync(0xffffffffu, v, o);
  if (lane==0) red[wid]=v;
  __syncthreads();
  float r = (threadIdx.x < (blockDim.x>>5)) ? red[threadIdx.x] : 0.f;
  if (wid==0){
    #pragma unroll
    for (int o=16;o>0;o>>=1) r += __shfl_down_sync(0xffffffffu, r, o);
    if (lane==0) red[0]=r;
  }
  __syncthreads();
  float out = red[0];
  __syncthreads();
  return out;
}

__global__ void ln_kernel(const float* __restrict__ x, const float* __restrict__ p0,
                          const float* __restrict__ p1, const float* __restrict__ p2,
                          const float* __restrict__ p3, const float* __restrict__ g,
                          const float* __restrict__ bia, float* out,
                          __nv_bfloat16* out_hi, __nv_bfloat16* out_lo,
                          __nv_bfloat16* out2_hi, __nv_bfloat16* out2_lo){
  int row = blockIdx.x, tid = threadIdx.x;
  float v[4]; float s=0.f;
  #pragma unroll
  for (int i=0;i<4;i++){
    size_t off = (size_t)row*HH + tid + i*256;
    float t = x[off]+p0[off]+p1[off]+p2[off]+p3[off];
    v[i]=t; s+=t;
  }
  float mean = block_sum(s)*(1.f/HH);
  float s2=0.f;
  #pragma unroll
  for (int i=0;i<4;i++){ float dd=v[i]-mean; s2+=dd*dd; }
  float inv = 1.f/sqrtf(block_sum(s2)*(1.f/HH) + 1e-5f);
  #pragma unroll
  for (int i=0;i<4;i++){
    int d = tid + i*256;
    size_t off = (size_t)row*HH + d;
    float y = (v[i]-mean)*inv*g[d] + bia[d];
    out[off]=y;
    __nv_bfloat16 h, l; split_bf(y, h, l);
    out_hi[off]=h; out_lo[off]=l;
    if (out2_hi){ out2_hi[off]=h; out2_lo[off]=l; }
  }
}

__global__ void wr_kernel(const float* __restrict__ Wr, float* out, int step){
  int b = blockIdx.x;
  float s=0.f;
  const float* hf = d_h + (size_t)b*S2*HH;
  for (int x = threadIdx.x; x < S2*HH; x += blockDim.x) s += hf[x]*Wr[x];
  s = block_sum(s);
  if (threadIdx.x==0) out[b*TACT+step] = 1.f/(1.f+expf(-s));
}

__global__ void wso_part(const float* __restrict__ Wso){
  int nb = blockIdx.x, sp = blockIdx.y, tid = threadIdx.x;
  int tx = tid&63, tg = tid>>6;
  __shared__ float Asm[32][33];
  __shared__ float Wsm[32][64];
  float acc[8];
  #pragma unroll
  for (int r=0;r<8;r++) acc[r]=0.f;
  const int kLen = (S2*HH)/WSOSPLIT, k0 = sp*kLen;
  for (int kc=0; kc<kLen; kc+=32){
    for (int i=tid; i<32*32; i+=256){
      int bq=i>>5, kk=i&31;
      Asm[bq][kk] = d_h[(size_t)bq*S2*HH + k0+kc+kk];
    }
    for (int i=tid; i<32*64; i+=256){
      int kk=i>>6, cc=i&63;
      Wsm[kk][cc] = Wso[(size_t)(k0+kc+kk)*HINN + nb*64 + cc];
    }
    __syncthreads();
    #pragma unroll
    for (int kk=0;kk<32;kk++){
      float w = Wsm[kk][tx];
      #pragma unroll
      for (int r=0;r<8;r++) acc[r] = fmaf(Asm[tg*8+r][kk], w, acc[r]);
    }
    __syncthreads();
  }
  #pragma unroll
  for (int r=0;r<8;r++)
    d_wsop[(size_t)sp*BB*HINN + (size_t)(tg*8+r)*HINN + nb*64 + tx] = acc[r];
}

__global__ void wso_reduce(float* out, int step){
  int b = blockIdx.x, n = threadIdx.x;
  float s=0.f;
  #pragma unroll
  for (int sp=0;sp<WSOSPLIT;sp++) s += d_wsop[(size_t)sp*BB*HINN + (size_t)b*HINN + n];
  s = fmaxf(s, 0.f);
  d_snew[b*HINN+n] = s;
  out[BB*TACT + (size_t)(b*TACT+step)*HINN + n] = s;
}

static void* sym(const void* s){ void* p = nullptr; cudaGetSymbolAddress(&p, s); return p; }

extern "C" void kernel_launch(void* const* d_in, const int* in_sizes, int n_in,
                              void* d_out, int out_size){
  (void)in_sizes; (void)n_in; (void)out_size;
  const float* hist_s=(const float*)d_in[0];
  const float* hist_a=(const float*)d_in[1];
  const float* s_in  =(const float*)d_in[2];
  const float* a_list=(const float*)d_in[3];
  const float* Ws =(const float*)d_in[4];
  const float* Wa =(const float*)d_in[5];
  const float* Wq =(const float*)d_in[6];
  const float* Wk =(const float*)d_in[7];
  const float* Wv =(const float*)d_in[8];
  const float* Wo =(const float*)d_in[9];
  const float* Wfc=(const float*)d_in[10];
  const float* ln1g=(const float*)d_in[11];
  const float* ln1b=(const float*)d_in[12];
  const float* ln2g=(const float*)d_in[13];
  const float* ln2b=(const float*)d_in[14];
  const float* Wr =(const float*)d_in[15];
  const float* Wso=(const float*)d_in[16];
  float* out = (float*)d_out;

  float* ph   =(float*)sym(d_h);
  float* pq   =(float*)sym(d_qb);
  float* pk   =(float*)sym(d_kb);
  float* pv   =(float*)sym(d_vb);
  float* pq2  =(float*)sym(d_q2);
  float* pk2  =(float*)sym(d_k2);
  float* pv2  =(float*)sym(d_v2);
  float* pp0  =(float*)sym(d_p0);
  float* pp1  =(float*)sym(d_p1);
  float* pp2  =(float*)sym(d_p2);
  float* pp3  =(float*)sym(d_p3);
  float* pae  =(float*)sym(d_aemb);
  float* psn  =(float*)sym(d_snew);
  float* ptok =(float*)sym(d_tokens);
  __nv_bfloat16* phh=(__nv_bfloat16*)sym(d_h_hi);
  __nv_bfloat16* phl=(__nv_bfloat16*)sym(d_h_lo);
  __nv_bfloat16* pch=(__nv_bfloat16*)sym(d_ctx_hi);
  __nv_bfloat16* pcl=(__nv_bfloat16*)sym(d_ctx_lo);
  __nv_bfloat16* pvh=(__nv_bfloat16*)sym(d_prev_hi);
  __nv_bfloat16* pvl=(__nv_bfloat16*)sym(d_prev_lo);
  __nv_bfloat16* pwh=(__nv_bfloat16*)sym(d_wt_hi);
  __nv_bfloat16* pwl=(__nv_bfloat16*)sym(d_wt_lo);

  cudaFuncSetAttribute(gemm_tc, cudaFuncAttributeMaxDynamicSharedMemorySize, TC_SMEM);

  pe_kernel<<<S2,256>>>();
  wcvt_kernel<<<dim3(32,32,NW),dim3(32,8)>>>(Wq, Wk, Wv, Wo, Wfc);

  {
    GemmArgs ga{};
    ga.ldc=HH; ga.act=1;
    ga.z[0]=GemmZ{hist_s, Ws, pq, 0, HINN, BB*THIST, HINN};
    ga.z[1]=GemmZ{hist_a, Wa, pk, 0, 64,   BB*THIST, 64};
    ga.z[2]=GemmZ{s_in,   Ws, pv, 0, HINN, BB,       HINN};
    ga.z[3]=GemmZ{a_list, Wa, pae,0, 64,   BB*TACT,  64};
    gemm_kernel<<<dim3(8,2,4),256>>>(ga);
  }
  init_tokens<<<dim3(S2,BB),256>>>();

  const size_t WSZ = (size_t)HH*HH;
  const size_t PSZ = (size_t)MR*HH;
  for (int i=0;i<TACT;i++){
    int L = 2*THIST + 2 + 2*i;
    build_h<<<dim3(S2,BB),256>>>(i);
    for (int j=0;j<NLAY;j++){
      const __nv_bfloat16* qkh = (i==0) ? phh : (pvh + (size_t)j*PSZ);
      const __nv_bfloat16* qkl = (i==0) ? phl : (pvl + (size_t)j*PSZ);
      {
        TCArgs ga{};
        ga.ldc=HH;
        const __nv_bfloat16* wqh = pwh + (size_t)(0*4+j)*WSZ;
        const __nv_bfloat16* wql = pwl + (size_t)(0*4+j)*WSZ;
        const __nv_bfloat16* wkh = pwh + (size_t)(1*4+j)*WSZ;
        const __nv_bfloat16* wkl = pwl + (size_t)(1*4+j)*WSZ;
        const __nv_bfloat16* wvh = pwh + (size_t)(2*4+j)*WSZ;
        const __nv_bfloat16* wvl = pwl + (size_t)(2*4+j)*WSZ;
        ga.z[0]=TCZ{qkh, qkl, wqh, wql, pq,  0,    HH/2};
        ga.z[1]=TCZ{qkh, qkl, wqh, wql, pq2, HH/2, HH};
        ga.z[2]=TCZ{qkh, qkl, wkh, wkl, pk,  0,    HH/2};
        ga.z[3]=TCZ{qkh, qkl, wkh, wkl, pk2, HH/2, HH};
        ga.z[4]=TCZ{phh, phl, wvh, wvl, pv,  0,    HH/2};
        ga.z[5]=TCZ{phh, phl, wvh, wvl, pv2, HH/2, HH};
        gemm_tc<<<dim3(8,8,6),256,TC_SMEM>>>(ga);
      }
      attn_kernel<<<BB*16,256>>>(L);
      {
        TCArgs ga{};
        ga.ldc=HH;
        const __nv_bfloat16* woh = pwh + (size_t)(3*4+j)*WSZ;
        const __nv_bfloat16* wol = pwl + (size_t)(3*4+j)*WSZ;
        ga.z[0]=TCZ{pch, pcl, woh, wol, pp0, 0,      HH/4};
        ga.z[1]=TCZ{pch, pcl, woh, wol, pp1, HH/4,   HH/2};
        ga.z[2]=TCZ{pch, pcl, woh, wol, pp2, HH/2,   3*HH/4};
        ga.z[3]=TCZ{pch, pcl, woh, wol, pp3, 3*HH/4, HH};
        gemm_tc<<<dim3(8,8,4),256,TC_SMEM>>>(ga);
      }
      ln_kernel<<<MR,256>>>(ph, pp0, pp1, pp2, pp3, ln1g+(size_t)j*HH, ln1b+(size_t)j*HH,
                            ph, phh, phl, nullptr, nullptr);
      {
        TCArgs ga{};
        ga.ldc=HH;
        const __nv_bfloat16* wfh = pwh + (size_t)(4*4+j)*WSZ;
        const __nv_bfloat16* wfl = pwl + (size_t)(4*4+j)*WSZ;
        ga.z[0]=TCZ{phh, phl, wfh, wfl, pp0, 0,      HH/4};
        ga.z[1]=TCZ{phh, phl, wfh, wfl, pp1, HH/4,   HH/2};
        ga.z[2]=TCZ{phh, phl, wfh, wfl, pp2, HH/2,   3*HH/4};
        ga.z[3]=TCZ{phh, phl, wfh, wfl, pp3, 3*HH/4, HH};
        gemm_tc<<<dim3(8,8,4),256,TC_SMEM>>>(ga);
      }
      ln_kernel<<<MR,256>>>(ph, pp0, pp1, pp2, pp3, ln2g+(size_t)j*HH, ln2b+(size_t)j*HH,
                            ph, phh, phl, pvh + (size_t)j*PSZ, pvl + (size_t)j*PSZ);
    }
    wr_kernel<<<BB,1024>>>(Wr, out, i);
    wso_part<<<dim3(8,WSOSPLIT),256>>>(Wso);
    wso_reduce<<<BB,HINN>>>(out, i);
    if (i+1 < TACT){
      int pos_s = 2*THIST + 2 + 2*i;
      GemmArgs ga{};
      ga.ldc=S2*HH; ga.act=1;
      ga.z[0]=GemmZ{psn, Ws, ptok + (size_t)pos_s*HH, 0, HINN, BB, HINN};
      gemm_kernel<<<dim3(8,1,1),256>>>(ga);
    }
  }
}